// round 5
// baseline (speedup 1.0000x reference)
#include <cuda_runtime.h>
#include <cstdint>

// Problem constants (fixed by dataset)
#define NV 100000
#define EV 1600000
#define FV 512
#define HV 256
#define NB_SCAN ((NV + 255) / 256)   // 391

// ---------------- scratch (static device globals; no allocation) ----------------
__device__ int   g_out_deg[NV];
__device__ int   g_in_deg[NV];
__device__ float g_norm_src[NV];
__device__ float g_norm_dst[NV];
__device__ int   g_offsets[NV];
__device__ int   g_cursor[NV];
__device__ int   g_part[NB_SCAN];
__device__ int   g_sorted_src[EV];
__device__ __align__(16) float g_y[(size_t)NV * HV];   // pre-aggregation activations
__device__ __align__(16) float g_h[(size_t)NV * HV];   // post-aggregation activations
__device__ float g_pooled[3 * HV];
__device__ float g_fd[2 * FV];

// ---------------- init / degrees / norms ----------------
__global__ void k_init() {
    int i = blockIdx.x * blockDim.x + threadIdx.x;
    if (i < NV) { g_out_deg[i] = 0; g_in_deg[i] = 0; g_cursor[i] = 0; }
    if (i < HV) { g_pooled[i] = 0.0f; g_pooled[HV + i] = __int_as_float(0xff800000); } // -inf
}

__global__ void k_deg(const int* __restrict__ src, const int* __restrict__ dst) {
    int e = blockIdx.x * blockDim.x + threadIdx.x;
    if (e < EV) {
        atomicAdd(&g_out_deg[src[e]], 1);
        atomicAdd(&g_in_deg[dst[e]], 1);
    }
}

__global__ void k_norm() {
    int i = blockIdx.x * blockDim.x + threadIdx.x;
    if (i < NV) {
        g_norm_src[i] = rsqrtf(fmaxf((float)g_out_deg[i], 1.0f));
        g_norm_dst[i] = rsqrtf(fmaxf((float)g_in_deg[i], 1.0f));
    }
}

// ---------------- exclusive scan of in_deg -> offsets (3 kernels) ----------------
__global__ void k_scan1() {
    __shared__ int s[256];
    int t = threadIdx.x;
    int i = blockIdx.x * 256 + t;
    int v = (i < NV) ? g_in_deg[i] : 0;
    s[t] = v;
    __syncthreads();
    #pragma unroll
    for (int off = 1; off < 256; off <<= 1) {
        int x = (t >= off) ? s[t - off] : 0;
        __syncthreads();
        s[t] += x;
        __syncthreads();
    }
    if (i < NV) g_offsets[i] = s[t] - v;        // exclusive within block
    if (t == 255) g_part[blockIdx.x] = s[255];  // block total
}

__global__ void k_scan2() {
    __shared__ int s[512];
    int t = threadIdx.x;
    int v = (t < NB_SCAN) ? g_part[t] : 0;
    s[t] = v;
    __syncthreads();
    #pragma unroll
    for (int off = 1; off < 512; off <<= 1) {
        int x = (t >= off) ? s[t - off] : 0;
        __syncthreads();
        s[t] += x;
        __syncthreads();
    }
    if (t < NB_SCAN) g_part[t] = s[t] - v;  // exclusive
}

__global__ void k_scan3() {
    int t = threadIdx.x;
    int i = blockIdx.x * 256 + t;
    if (i < NV) g_offsets[i] += g_part[blockIdx.x];
}

// ---------------- scatter edges into CSR-by-dst ----------------
__global__ void k_scatter(const int* __restrict__ src, const int* __restrict__ dst) {
    int e = blockIdx.x * blockDim.x + threadIdx.x;
    if (e < EV) {
        int d = dst[e];
        int p = atomicAdd(&g_cursor[d], 1);
        g_sorted_src[g_offsets[d] + p] = src[e];
    }
}

// ---------------- tf32 tensor-core GEMM (double-buffered, 64x64 warp tiles) ----------------
// C[M,256] = ((A @ B) * norm_src[:,None])
// 128x128 block tile, 4 warps (2m x 2n), each warp 64x64 via m16n8k8 tf32 mma.
#define SMS 136   // smem row stride (uint32)

__device__ __forceinline__ uint32_t f2tf(float f) {
    uint32_t u;
    asm("cvt.rna.tf32.f32 %0, %1;" : "=r"(u) : "f"(f));
    return u;
}

__device__ __forceinline__ void mma_tf32(float* c, const uint32_t* a, const uint32_t* b) {
    asm volatile(
        "mma.sync.aligned.m16n8k8.row.col.f32.tf32.tf32.f32 "
        "{%0,%1,%2,%3}, {%4,%5,%6,%7}, {%8,%9}, {%0,%1,%2,%3};"
        : "+f"(c[0]), "+f"(c[1]), "+f"(c[2]), "+f"(c[3])
        : "r"(a[0]), "r"(a[1]), "r"(a[2]), "r"(a[3]), "r"(b[0]), "r"(b[1]));
}

__global__ __launch_bounds__(128) void k_gemm_tf32(const float* __restrict__ A,
                                                   const float* __restrict__ B,
                                                   float* __restrict__ C,
                                                   int M, int K) {
    __shared__ uint32_t As[2][16 * SMS];   // transposed: [k][m]
    __shared__ uint32_t Bs[2][16 * SMS];   // [k][n]

    int tid  = threadIdx.x;
    int brow = blockIdx.y * 128;
    int bcol = blockIdx.x * 128;

    // ---- A-load mapping: each thread loads one full row (16 floats = 4 float4) ----
    int arow = tid;                      // 0..127
    int gr = brow + arow;
    bool v = gr < M;
    const float* Ap = A + (size_t)(v ? gr : 0) * K;

    // ---- B-load mapping: thread loads k = bk, bk+4, bk+8, bk+12 at col bc ----
    int bk = tid >> 5;                   // 0..3
    int bc = (tid & 31) * 4;             // 0..124
    const float* Bp = B + (size_t)bk * HV + bcol + bc;

    // ---- warp tiling: 4 warps, 2m x 2n, each 64x64 ----
    int wid  = tid >> 5, lane = tid & 31;
    int wm = (wid & 1) * 64;
    int wn = (wid >> 1) * 64;
    int r  = lane >> 2;                  // 0..7
    int cq = lane & 3;                   // 0..3

    float acc[4][8][4];
    #pragma unroll
    for (int i = 0; i < 4; i++)
        #pragma unroll
        for (int j = 0; j < 8; j++)
            #pragma unroll
            for (int q = 0; q < 4; q++) acc[i][j][q] = 0.0f;

    // initial prefetch (tile k0 = 0)
    float4 pa[4], pb[4];
    #pragma unroll
    for (int i = 0; i < 4; i++) {
        pa[i] = v ? *(const float4*)(Ap + i * 4) : make_float4(0,0,0,0);
        pb[i] = *(const float4*)(Bp + (size_t)(i * 4) * HV);
    }

    int buf = 0;
    for (int k0 = 0; k0 < K; k0 += 16) {
        // store prefetched tiles (RNA tf32) into smem[buf]
        uint32_t* Asb = As[buf];
        uint32_t* Bsb = Bs[buf];
        #pragma unroll
        for (int i = 0; i < 4; i++) {
            Asb[(i * 4 + 0) * SMS + arow] = f2tf(pa[i].x);
            Asb[(i * 4 + 1) * SMS + arow] = f2tf(pa[i].y);
            Asb[(i * 4 + 2) * SMS + arow] = f2tf(pa[i].z);
            Asb[(i * 4 + 3) * SMS + arow] = f2tf(pa[i].w);
            *(uint4*)&Bsb[(bk + i * 4) * SMS + bc] =
                make_uint4(f2tf(pb[i].x), f2tf(pb[i].y), f2tf(pb[i].z), f2tf(pb[i].w));
        }
        __syncthreads();

        // prefetch next tile while computing this one
        int kn = k0 + 16;
        if (kn < K) {
            #pragma unroll
            for (int i = 0; i < 4; i++) {
                pa[i] = v ? *(const float4*)(Ap + kn + i * 4) : make_float4(0,0,0,0);
                pb[i] = *(const float4*)(Bp + (size_t)(kn + i * 4) * HV);
            }
        }

        #pragma unroll
        for (int ks = 0; ks < 2; ks++) {
            uint32_t a[4][4], b[8][2];
            #pragma unroll
            for (int mt = 0; mt < 4; mt++) {
                int mbase = wm + mt * 16 + r;
                a[mt][0] = Asb[(ks * 8 + cq)     * SMS + mbase];
                a[mt][1] = Asb[(ks * 8 + cq)     * SMS + mbase + 8];
                a[mt][2] = Asb[(ks * 8 + cq + 4) * SMS + mbase];
                a[mt][3] = Asb[(ks * 8 + cq + 4) * SMS + mbase + 8];
            }
            #pragma unroll
            for (int nt = 0; nt < 8; nt++) {
                int nbase = wn + nt * 8 + r;
                b[nt][0] = Bsb[(ks * 8 + cq)     * SMS + nbase];
                b[nt][1] = Bsb[(ks * 8 + cq + 4) * SMS + nbase];
            }
            #pragma unroll
            for (int mt = 0; mt < 4; mt++)
                #pragma unroll
                for (int nt = 0; nt < 8; nt++)
                    mma_tf32(acc[mt][nt], a[mt], b[nt]);
        }
        buf ^= 1;
        __syncthreads();
    }

    // ---- epilogue: scale by norm_src[row], store fp32 ----
    #pragma unroll
    for (int mt = 0; mt < 4; mt++) {
        int row0 = brow + wm + mt * 16 + r;
        int row1 = row0 + 8;
        float s0 = (row0 < M) ? g_norm_src[row0] : 0.0f;
        float s1 = (row1 < M) ? g_norm_src[row1] : 0.0f;
        #pragma unroll
        for (int nt = 0; nt < 8; nt++) {
            int col = bcol + wn + nt * 8 + cq * 2;
            if (row0 < M) *(float2*)(C + (size_t)row0 * HV + col) =
                make_float2(acc[mt][nt][0] * s0, acc[mt][nt][1] * s0);
            if (row1 < M) *(float2*)(C + (size_t)row1 * HV + col) =
                make_float2(acc[mt][nt][2] * s1, acc[mt][nt][3] * s1);
        }
    }
}

// ---------------- aggregation over a 128-column half (L2-resident working set) ----
// O[n, cb:cb+128] = leaky( norm_dst[n] * sum_{e in CSR(n)} Y[src_e, cb:cb+128] + bias )
// one warp per node, 4 cols per thread, 4-edge unroll (MLP=4).
__global__ void k_agg_half(const float* __restrict__ Y, const float* __restrict__ bias,
                           float* __restrict__ O, int cb) {
    int node = blockIdx.x;
    int t = threadIdx.x;            // 0..31
    int col = cb + t * 4;
    int start = g_offsets[node];
    int cnt   = g_in_deg[node];

    float4 a = make_float4(0,0,0,0), b = make_float4(0,0,0,0);
    float4 c = make_float4(0,0,0,0), d = make_float4(0,0,0,0);
    int e = 0;
    for (; e + 4 <= cnt; e += 4) {
        int s0 = g_sorted_src[start + e];
        int s1 = g_sorted_src[start + e + 1];
        int s2 = g_sorted_src[start + e + 2];
        int s3 = g_sorted_src[start + e + 3];
        float4 x0 = *(const float4*)(Y + (size_t)s0 * HV + col);
        float4 x1 = *(const float4*)(Y + (size_t)s1 * HV + col);
        float4 x2 = *(const float4*)(Y + (size_t)s2 * HV + col);
        float4 x3 = *(const float4*)(Y + (size_t)s3 * HV + col);
        a.x += x0.x; a.y += x0.y; a.z += x0.z; a.w += x0.w;
        b.x += x1.x; b.y += x1.y; b.z += x1.z; b.w += x1.w;
        c.x += x2.x; c.y += x2.y; c.z += x2.z; c.w += x2.w;
        d.x += x3.x; d.y += x3.y; d.z += x3.z; d.w += x3.w;
    }
    for (; e < cnt; e++) {
        int s0 = g_sorted_src[start + e];
        float4 x0 = *(const float4*)(Y + (size_t)s0 * HV + col);
        a.x += x0.x; a.y += x0.y; a.z += x0.z; a.w += x0.w;
    }
    a.x += b.x + c.x + d.x;
    a.y += b.y + c.y + d.y;
    a.z += b.z + c.z + d.z;
    a.w += b.w + c.w + d.w;

    float nd = g_norm_dst[node];
    float4 bb = *(const float4*)(bias + col);
    float4 o;
    o.x = a.x * nd + bb.x;  o.x = (o.x >= 0.0f) ? o.x : 0.01f * o.x;
    o.y = a.y * nd + bb.y;  o.y = (o.y >= 0.0f) ? o.y : 0.01f * o.y;
    o.z = a.z * nd + bb.z;  o.z = (o.z >= 0.0f) ? o.z : 0.01f * o.z;
    o.w = a.w * nd + bb.w;  o.w = (o.w >= 0.0f) ? o.w : 0.01f * o.w;
    *(float4*)(O + (size_t)node * HV + col) = o;
}

// ---------------- pooling: column-wise sum and max of g_h ----------------
__device__ __forceinline__ void atomicMaxF(float* addr, float val) {
    int* ia = (int*)addr;
    int old = *ia;
    while (__int_as_float(old) < val) {
        int assumed = old;
        old = atomicCAS(ia, assumed, __float_as_int(val));
        if (old == assumed) break;
    }
}

__global__ void k_pool() {
    int t = threadIdx.x;  // 256
    float sum = 0.0f;
    float mx  = __int_as_float(0xff800000);
    for (int r = blockIdx.x; r < NV; r += gridDim.x) {
        float v = g_h[(size_t)r * HV + t];
        sum += v;
        mx = fmaxf(mx, v);
    }
    atomicAdd(&g_pooled[t], sum);
    atomicMaxF(&g_pooled[HV + t], mx);
}

__global__ void k_pick(const int* __restrict__ node_index) {
    int t = threadIdx.x;  // 256
    int ni = node_index[0];
    g_pooled[2 * HV + t] = g_h[(size_t)ni * HV + t];
}

// ---------------- head GEMV: fd[1024] = pooled[768] @ Wg[768,1024] + bg ----------------
__global__ void k_gemv(const float* __restrict__ Wg, const float* __restrict__ bg) {
    __shared__ float sp[3 * HV];
    int t = threadIdx.x;  // 256, grid 4
    for (int i = t; i < 3 * HV; i += 256) sp[i] = g_pooled[i];
    __syncthreads();
    int j = blockIdx.x * 256 + t;
    float acc = bg[j];
    #pragma unroll 8
    for (int k = 0; k < 3 * HV; k++) acc += sp[k] * Wg[(size_t)k * (2 * FV) + j];
    g_fd[j] = acc;
}

// ---------------- epilogue: reparam + log_prob ----------------
__global__ void k_final(const float* __restrict__ eps, float* __restrict__ out) {
    __shared__ float red[FV];
    int t = threadIdx.x;  // 512
    float mu = g_fd[t];
    float sg = fabsf(g_fd[FV + t]);
    float fn = mu + sg * eps[t];
    out[t]          = fn;   // feat_new
    out[FV + t]     = mu;   // mu
    out[2 * FV + t] = sg;   // sigma
    float z = (fn - mu) / sg;
    const float half_log2pi = 0.9189385332046727f;  // 0.5*log(2*pi)
    float term = -0.5f * z * z - logf(sg) - half_log2pi;
    red[t] = term;
    __syncthreads();
    #pragma unroll
    for (int o = 256; o > 0; o >>= 1) {
        if (t < o) red[t] += red[t + o];
        __syncthreads();
    }
    if (t == 0) out[3 * FV] = red[0] / (float)FV;  // log_prob
}

// ---------------- launch ----------------
extern "C" void kernel_launch(void* const* d_in, const int* in_sizes, int n_in,
                              void* d_out, int out_size) {
    const float* feat       = (const float*)d_in[0];
    const int*   src        = (const int*)  d_in[1];
    const int*   dst        = (const int*)  d_in[2];
    const int*   node_index = (const int*)  d_in[3];
    const float* W1         = (const float*)d_in[4];
    const float* b1         = (const float*)d_in[5];
    const float* W2         = (const float*)d_in[6];
    const float* b2         = (const float*)d_in[7];
    const float* Wg         = (const float*)d_in[8];
    const float* bg         = (const float*)d_in[9];
    const float* eps        = (const float*)d_in[10];
    float*       out        = (float*)d_out;

    void *yp_v, *hp_v;
    cudaGetSymbolAddress(&yp_v, g_y);
    cudaGetSymbolAddress(&hp_v, g_h);
    float* yp = (float*)yp_v;
    float* hp = (float*)hp_v;

    dim3 gemm_grid(2, (NV + 127) / 128);

    k_init<<<(NV + 255) / 256, 256>>>();
    k_deg<<<(EV + 255) / 256, 256>>>(src, dst);
    k_norm<<<(NV + 255) / 256, 256>>>();
    // GEMM1 early (launch #4) so the fixed-index ncu capture profiles it
    k_gemm_tf32<<<gemm_grid, 128>>>(feat, W1, yp, NV, FV);
    k_scan1<<<NB_SCAN, 256>>>();
    k_scan2<<<1, 512>>>();
    k_scan3<<<NB_SCAN, 256>>>();
    k_scatter<<<(EV + 255) / 256, 256>>>(src, dst);

    // layer 1 aggregation: two column-half passes (each 51MB working set, L2-resident)
    k_agg_half<<<NV, 32>>>(yp, b1, hp, 0);
    k_agg_half<<<NV, 32>>>(yp, b1, hp, 128);
    // layer 2
    k_gemm_tf32<<<gemm_grid, 128>>>(hp, W2, yp, NV, HV);
    k_agg_half<<<NV, 32>>>(yp, b2, hp, 0);
    k_agg_half<<<NV, 32>>>(yp, b2, hp, 128);

    k_pool<<<256, 256>>>();
    k_pick<<<1, 256>>>(node_index);
    k_gemv<<<4, 256>>>(Wg, bg);
    k_final<<<1, 512>>>(eps, out);
}

// round 6
// speedup vs baseline: 1.1669x; 1.1669x over previous
#include <cuda_runtime.h>
#include <cuda_fp16.h>
#include <cstdint>

// Problem constants (fixed by dataset)
#define NV 100000
#define EV 1600000
#define FV 512
#define HV 256
#define NB_SCAN ((NV + 255) / 256)   // 391

// ---------------- scratch (static device globals; no allocation) ----------------
__device__ int   g_out_deg[NV];
__device__ int   g_in_deg[NV];
__device__ float g_norm_src[NV];
__device__ float g_norm_dst[NV];
__device__ int   g_offsets[NV];
__device__ int   g_cursor[NV];
__device__ int   g_part[NB_SCAN];
__device__ int   g_sorted_src[EV];
__device__ __align__(16) __half g_yh[(size_t)NV * HV];  // pre-aggregation activations (fp16 RN)
__device__ __align__(16) float  g_h[(size_t)NV * HV];   // post-aggregation activations (fp32)
__device__ float g_pooled[3 * HV];
__device__ float g_fd[2 * FV];

// ---------------- init / degrees / norms ----------------
__global__ void k_init() {
    int i = blockIdx.x * blockDim.x + threadIdx.x;
    if (i < NV) { g_out_deg[i] = 0; g_in_deg[i] = 0; g_cursor[i] = 0; }
    if (i < HV) { g_pooled[i] = 0.0f; g_pooled[HV + i] = __int_as_float(0xff800000); } // -inf
}

__global__ void k_deg(const int* __restrict__ src, const int* __restrict__ dst) {
    int e = blockIdx.x * blockDim.x + threadIdx.x;
    if (e < EV) {
        atomicAdd(&g_out_deg[src[e]], 1);
        atomicAdd(&g_in_deg[dst[e]], 1);
    }
}

__global__ void k_norm() {
    int i = blockIdx.x * blockDim.x + threadIdx.x;
    if (i < NV) {
        g_norm_src[i] = rsqrtf(fmaxf((float)g_out_deg[i], 1.0f));
        g_norm_dst[i] = rsqrtf(fmaxf((float)g_in_deg[i], 1.0f));
    }
}

// ---------------- exclusive scan of in_deg -> offsets (3 kernels) ----------------
__global__ void k_scan1() {
    __shared__ int s[256];
    int t = threadIdx.x;
    int i = blockIdx.x * 256 + t;
    int v = (i < NV) ? g_in_deg[i] : 0;
    s[t] = v;
    __syncthreads();
    #pragma unroll
    for (int off = 1; off < 256; off <<= 1) {
        int x = (t >= off) ? s[t - off] : 0;
        __syncthreads();
        s[t] += x;
        __syncthreads();
    }
    if (i < NV) g_offsets[i] = s[t] - v;        // exclusive within block
    if (t == 255) g_part[blockIdx.x] = s[255];  // block total
}

__global__ void k_scan2() {
    __shared__ int s[512];
    int t = threadIdx.x;
    int v = (t < NB_SCAN) ? g_part[t] : 0;
    s[t] = v;
    __syncthreads();
    #pragma unroll
    for (int off = 1; off < 512; off <<= 1) {
        int x = (t >= off) ? s[t - off] : 0;
        __syncthreads();
        s[t] += x;
        __syncthreads();
    }
    if (t < NB_SCAN) g_part[t] = s[t] - v;  // exclusive
}

__global__ void k_scan3() {
    int t = threadIdx.x;
    int i = blockIdx.x * 256 + t;
    if (i < NV) g_offsets[i] += g_part[blockIdx.x];
}

// ---------------- scatter edges into CSR-by-dst ----------------
__global__ void k_scatter(const int* __restrict__ src, const int* __restrict__ dst) {
    int e = blockIdx.x * blockDim.x + threadIdx.x;
    if (e < EV) {
        int d = dst[e];
        int p = atomicAdd(&g_cursor[d], 1);
        g_sorted_src[g_offsets[d] + p] = src[e];
    }
}

// ---------------- tf32 tensor-core GEMM (round-4 config: 256 thr, 32x64 warp tiles) ----
// C[M,256] = ((A @ B) * norm_src[:,None]) stored as fp16 (RN)
#define SMS 136   // smem row stride (uint32)

__device__ __forceinline__ uint32_t f2tf(float f) {
    uint32_t u;
    asm("cvt.rna.tf32.f32 %0, %1;" : "=r"(u) : "f"(f));
    return u;
}

__device__ __forceinline__ void mma_tf32(float* c, const uint32_t* a, const uint32_t* b) {
    asm volatile(
        "mma.sync.aligned.m16n8k8.row.col.f32.tf32.tf32.f32 "
        "{%0,%1,%2,%3}, {%4,%5,%6,%7}, {%8,%9}, {%0,%1,%2,%3};"
        : "+f"(c[0]), "+f"(c[1]), "+f"(c[2]), "+f"(c[3])
        : "r"(a[0]), "r"(a[1]), "r"(a[2]), "r"(a[3]), "r"(b[0]), "r"(b[1]));
}

__global__ __launch_bounds__(256) void k_gemm_tf32(const float* __restrict__ A,
                                                   const float* __restrict__ B,
                                                   __half* __restrict__ C,
                                                   int M, int K) {
    __shared__ uint32_t As[2][16 * SMS];   // transposed: [k][m]
    __shared__ uint32_t Bs[2][16 * SMS];   // [k][n]

    int tid  = threadIdx.x;
    int brow = blockIdx.y * 128;
    int bcol = blockIdx.x * 128;

    // ---- A-load mapping: 128x16 floats = 512 float4, 2 per thread ----
    int arow0 = tid >> 2;               // 0..63
    int arow1 = arow0 + 64;             // 64..127
    int ac0   = (tid & 3) * 4;          // k-offset within tile: 0,4,8,12
    int gr0 = brow + arow0, gr1 = brow + arow1;
    bool v0 = gr0 < M, v1 = gr1 < M;
    const float* Ap0 = A + (size_t)(v0 ? gr0 : 0) * K + ac0;
    const float* Ap1 = A + (size_t)(v1 ? gr1 : 0) * K + ac0;

    // ---- B-load mapping: 16x128 floats = 512 float4, 2 per thread ----
    int bk0 = tid >> 5;                 // 0..7  (second half: +8)
    int bc0 = (tid & 31) * 4;           // 0..124
    const float* Bp0 = B + (size_t)bk0 * HV + bcol + bc0;
    const float* Bp1 = B + (size_t)(bk0 + 8) * HV + bcol + bc0;

    // ---- warp tiling: 8 warps (4m x 2n), each 32x64 ----
    int wid  = tid >> 5, lane = tid & 31;
    int wm = (wid & 3) * 32;
    int wn = (wid >> 2) * 64;
    int r  = lane >> 2;                 // 0..7
    int cq = lane & 3;                  // 0..3

    float acc[2][8][4];
    #pragma unroll
    for (int i = 0; i < 2; i++)
        #pragma unroll
        for (int j = 0; j < 8; j++)
            #pragma unroll
            for (int q = 0; q < 4; q++) acc[i][j][q] = 0.0f;

    // initial prefetch (tile k0 = 0)
    float4 pa0 = v0 ? *(const float4*)(Ap0) : make_float4(0,0,0,0);
    float4 pa1 = v1 ? *(const float4*)(Ap1) : make_float4(0,0,0,0);
    float4 pb0 = *(const float4*)(Bp0);
    float4 pb1 = *(const float4*)(Bp1);

    int buf = 0;
    for (int k0 = 0; k0 < K; k0 += 16) {
        uint32_t* Asb = As[buf];
        uint32_t* Bsb = Bs[buf];
        Asb[(ac0 + 0) * SMS + arow0] = f2tf(pa0.x);
        Asb[(ac0 + 1) * SMS + arow0] = f2tf(pa0.y);
        Asb[(ac0 + 2) * SMS + arow0] = f2tf(pa0.z);
        Asb[(ac0 + 3) * SMS + arow0] = f2tf(pa0.w);
        Asb[(ac0 + 0) * SMS + arow1] = f2tf(pa1.x);
        Asb[(ac0 + 1) * SMS + arow1] = f2tf(pa1.y);
        Asb[(ac0 + 2) * SMS + arow1] = f2tf(pa1.z);
        Asb[(ac0 + 3) * SMS + arow1] = f2tf(pa1.w);
        *(uint4*)&Bsb[bk0 * SMS + bc0]       = make_uint4(f2tf(pb0.x), f2tf(pb0.y), f2tf(pb0.z), f2tf(pb0.w));
        *(uint4*)&Bsb[(bk0 + 8) * SMS + bc0] = make_uint4(f2tf(pb1.x), f2tf(pb1.y), f2tf(pb1.z), f2tf(pb1.w));
        __syncthreads();

        int kn = k0 + 16;
        if (kn < K) {
            pa0 = v0 ? *(const float4*)(Ap0 + kn) : make_float4(0,0,0,0);
            pa1 = v1 ? *(const float4*)(Ap1 + kn) : make_float4(0,0,0,0);
            pb0 = *(const float4*)(Bp0 + (size_t)kn * HV);
            pb1 = *(const float4*)(Bp1 + (size_t)kn * HV);
        }

        #pragma unroll
        for (int ks = 0; ks < 2; ks++) {
            uint32_t a[2][4], b[8][2];
            #pragma unroll
            for (int mt = 0; mt < 2; mt++) {
                int mbase = wm + mt * 16 + r;
                a[mt][0] = Asb[(ks * 8 + cq)     * SMS + mbase];
                a[mt][1] = Asb[(ks * 8 + cq)     * SMS + mbase + 8];
                a[mt][2] = Asb[(ks * 8 + cq + 4) * SMS + mbase];
                a[mt][3] = Asb[(ks * 8 + cq + 4) * SMS + mbase + 8];
            }
            #pragma unroll
            for (int nt = 0; nt < 8; nt++) {
                int nbase = wn + nt * 8 + r;
                b[nt][0] = Bsb[(ks * 8 + cq)     * SMS + nbase];
                b[nt][1] = Bsb[(ks * 8 + cq + 4) * SMS + nbase];
            }
            #pragma unroll
            for (int mt = 0; mt < 2; mt++)
                #pragma unroll
                for (int nt = 0; nt < 8; nt++)
                    mma_tf32(acc[mt][nt], a[mt], b[nt]);
        }
        buf ^= 1;
        __syncthreads();
    }

    // ---- epilogue: scale by norm_src[row], convert fp16 RN, store ----
    #pragma unroll
    for (int mt = 0; mt < 2; mt++) {
        int row0 = brow + wm + mt * 16 + r;
        int row1 = row0 + 8;
        float s0 = (row0 < M) ? g_norm_src[row0] : 0.0f;
        float s1 = (row1 < M) ? g_norm_src[row1] : 0.0f;
        #pragma unroll
        for (int nt = 0; nt < 8; nt++) {
            int col = bcol + wn + nt * 8 + cq * 2;
            if (row0 < M)
                *(__half2*)(C + (size_t)row0 * HV + col) =
                    __floats2half2_rn(acc[mt][nt][0] * s0, acc[mt][nt][1] * s0);
            if (row1 < M)
                *(__half2*)(C + (size_t)row1 * HV + col) =
                    __floats2half2_rn(acc[mt][nt][2] * s1, acc[mt][nt][3] * s1);
        }
    }
}

// ---------------- aggregation: h[n] = leaky( norm_dst[n]*sum_{e in CSR(n)} Y[src_e] + bias ) ----
// Y fp16 (256 cols = 64 uint2/row); 64 threads/node, 4 cols each; 4-edge unroll, fp32 accum.
__global__ void k_agg(const __half* __restrict__ Y, const float* __restrict__ bias,
                      float* __restrict__ O) {
    int node = blockIdx.x;
    int t = threadIdx.x;            // 0..63
    int start = g_offsets[node];
    int cnt   = g_in_deg[node];
    const uint2* Yv = (const uint2*)Y;   // row stride = 64 uint2

    float a0=0.f,a1=0.f,a2=0.f,a3=0.f;
    float b0=0.f,b1=0.f,b2=0.f,b3=0.f;
    float c0=0.f,c1=0.f,c2=0.f,c3=0.f;
    float d0=0.f,d1=0.f,d2=0.f,d3=0.f;
    int e = 0;
    for (; e + 4 <= cnt; e += 4) {
        int s0 = g_sorted_src[start + e];
        int s1 = g_sorted_src[start + e + 1];
        int s2 = g_sorted_src[start + e + 2];
        int s3 = g_sorted_src[start + e + 3];
        uint2 u0 = Yv[(size_t)s0 * 64 + t];
        uint2 u1 = Yv[(size_t)s1 * 64 + t];
        uint2 u2 = Yv[(size_t)s2 * 64 + t];
        uint2 u3 = Yv[(size_t)s3 * 64 + t];
        float2 x00 = __half22float2(*(__half2*)&u0.x), x01 = __half22float2(*(__half2*)&u0.y);
        float2 x10 = __half22float2(*(__half2*)&u1.x), x11 = __half22float2(*(__half2*)&u1.y);
        float2 x20 = __half22float2(*(__half2*)&u2.x), x21 = __half22float2(*(__half2*)&u2.y);
        float2 x30 = __half22float2(*(__half2*)&u3.x), x31 = __half22float2(*(__half2*)&u3.y);
        a0 += x00.x; a1 += x00.y; a2 += x01.x; a3 += x01.y;
        b0 += x10.x; b1 += x10.y; b2 += x11.x; b3 += x11.y;
        c0 += x20.x; c1 += x20.y; c2 += x21.x; c3 += x21.y;
        d0 += x30.x; d1 += x30.y; d2 += x31.x; d3 += x31.y;
    }
    for (; e < cnt; e++) {
        int s0 = g_sorted_src[start + e];
        uint2 u0 = Yv[(size_t)s0 * 64 + t];
        float2 x00 = __half22float2(*(__half2*)&u0.x), x01 = __half22float2(*(__half2*)&u0.y);
        a0 += x00.x; a1 += x00.y; a2 += x01.x; a3 += x01.y;
    }
    a0 += b0 + c0 + d0;
    a1 += b1 + c1 + d1;
    a2 += b2 + c2 + d2;
    a3 += b3 + c3 + d3;

    float nd = g_norm_dst[node];
    float4 bb = *(const float4*)(bias + t * 4);
    float4 o;
    o.x = a0 * nd + bb.x;  o.x = (o.x >= 0.0f) ? o.x : 0.01f * o.x;
    o.y = a1 * nd + bb.y;  o.y = (o.y >= 0.0f) ? o.y : 0.01f * o.y;
    o.z = a2 * nd + bb.z;  o.z = (o.z >= 0.0f) ? o.z : 0.01f * o.z;
    o.w = a3 * nd + bb.w;  o.w = (o.w >= 0.0f) ? o.w : 0.01f * o.w;
    *(float4*)(O + (size_t)node * HV + t * 4) = o;
}

// ---------------- pooling: column-wise sum and max of g_h ----------------
__device__ __forceinline__ void atomicMaxF(float* addr, float val) {
    int* ia = (int*)addr;
    int old = *ia;
    while (__int_as_float(old) < val) {
        int assumed = old;
        old = atomicCAS(ia, assumed, __float_as_int(val));
        if (old == assumed) break;
    }
}

__global__ void k_pool() {
    int t = threadIdx.x;  // 256
    float sum = 0.0f;
    float mx  = __int_as_float(0xff800000);
    for (int r = blockIdx.x; r < NV; r += gridDim.x) {
        float v = g_h[(size_t)r * HV + t];
        sum += v;
        mx = fmaxf(mx, v);
    }
    atomicAdd(&g_pooled[t], sum);
    atomicMaxF(&g_pooled[HV + t], mx);
}

__global__ void k_pick(const int* __restrict__ node_index) {
    int t = threadIdx.x;  // 256
    int ni = node_index[0];
    g_pooled[2 * HV + t] = g_h[(size_t)ni * HV + t];
}

// ---------------- head GEMV: fd[1024] = pooled[768] @ Wg[768,1024] + bg ----------------
__global__ void k_gemv(const float* __restrict__ Wg, const float* __restrict__ bg) {
    __shared__ float sp[3 * HV];
    int t = threadIdx.x;  // 256, grid 4
    for (int i = t; i < 3 * HV; i += 256) sp[i] = g_pooled[i];
    __syncthreads();
    int j = blockIdx.x * 256 + t;
    float acc = bg[j];
    #pragma unroll 8
    for (int k = 0; k < 3 * HV; k++) acc += sp[k] * Wg[(size_t)k * (2 * FV) + j];
    g_fd[j] = acc;
}

// ---------------- epilogue: reparam + log_prob ----------------
__global__ void k_final(const float* __restrict__ eps, float* __restrict__ out) {
    __shared__ float red[FV];
    int t = threadIdx.x;  // 512
    float mu = g_fd[t];
    float sg = fabsf(g_fd[FV + t]);
    float fn = mu + sg * eps[t];
    out[t]          = fn;   // feat_new
    out[FV + t]     = mu;   // mu
    out[2 * FV + t] = sg;   // sigma
    float z = (fn - mu) / sg;
    const float half_log2pi = 0.9189385332046727f;  // 0.5*log(2*pi)
    float term = -0.5f * z * z - logf(sg) - half_log2pi;
    red[t] = term;
    __syncthreads();
    #pragma unroll
    for (int o = 256; o > 0; o >>= 1) {
        if (t < o) red[t] += red[t + o];
        __syncthreads();
    }
    if (t == 0) out[3 * FV] = red[0] / (float)FV;  // log_prob
}

// ---------------- launch ----------------
extern "C" void kernel_launch(void* const* d_in, const int* in_sizes, int n_in,
                              void* d_out, int out_size) {
    const float* feat       = (const float*)d_in[0];
    const int*   src        = (const int*)  d_in[1];
    const int*   dst        = (const int*)  d_in[2];
    const int*   node_index = (const int*)  d_in[3];
    const float* W1         = (const float*)d_in[4];
    const float* b1         = (const float*)d_in[5];
    const float* W2         = (const float*)d_in[6];
    const float* b2         = (const float*)d_in[7];
    const float* Wg         = (const float*)d_in[8];
    const float* bg         = (const float*)d_in[9];
    const float* eps        = (const float*)d_in[10];
    float*       out        = (float*)d_out;

    void *yp_v, *hp_v;
    cudaGetSymbolAddress(&yp_v, g_yh);
    cudaGetSymbolAddress(&hp_v, g_h);
    __half* yp = (__half*)yp_v;
    float*  hp = (float*)hp_v;

    dim3 gemm_grid(2, (NV + 127) / 128);

    k_init<<<(NV + 255) / 256, 256>>>();
    k_deg<<<(EV + 255) / 256, 256>>>(src, dst);
    k_norm<<<(NV + 255) / 256, 256>>>();
    // GEMM1 early (launch #4) so the fixed-index ncu capture profiles it
    k_gemm_tf32<<<gemm_grid, 256>>>(feat, W1, yp, NV, FV);
    k_scan1<<<NB_SCAN, 256>>>();
    k_scan2<<<1, 512>>>();
    k_scan3<<<NB_SCAN, 256>>>();
    k_scatter<<<(EV + 255) / 256, 256>>>(src, dst);

    k_agg<<<NV, 64>>>(yp, b1, hp);
    k_gemm_tf32<<<gemm_grid, 256>>>(hp, W2, yp, NV, HV);
    k_agg<<<NV, 64>>>(yp, b2, hp);

    k_pool<<<256, 256>>>();
    k_pick<<<1, 256>>>(node_index);
    k_gemv<<<4, 256>>>(Wg, bg);
    k_final<<<1, 512>>>(eps, out);
}

// round 7
// speedup vs baseline: 1.2362x; 1.0593x over previous
#include <cuda_runtime.h>
#include <cuda_fp16.h>
#include <cstdint>

// Problem constants (fixed by dataset)
#define NV 100000
#define EV 1600000
#define FV 512
#define HV 256
#define NB_SCAN ((NV + 255) / 256)   // 391

// ---------------- scratch (static device globals; no allocation) ----------------
__device__ int   g_out_deg[NV];
__device__ int   g_in_deg[NV];
__device__ float g_norm_src[NV];
__device__ float g_norm_dst[NV];
__device__ int   g_offsets[NV];
__device__ int   g_cursor[NV];
__device__ int   g_part[NB_SCAN];
__device__ int   g_sorted_src[EV];
__device__ __align__(16) __half g_yh[(size_t)NV * HV];  // pre-aggregation activations (fp16 RN)
__device__ __align__(16) float  g_h[(size_t)NV * HV];   // post-aggregation activations (fp32)
__device__ __align__(16) uint32_t g_wt1[HV * (FV / 2)]; // W1^T as fp16x2: [n][k/2], k-contiguous
__device__ __align__(16) uint32_t g_wt2[HV * (HV / 2)]; // W2^T as fp16x2
__device__ float g_pooled[3 * HV];
__device__ float g_fd[2 * FV];

// ---------------- init + degrees-zero + weight transpose/convert (one kernel) -----
// i < NV           : zero counters
// i < HV*FV/2      : build Wt1 word (n, kp) from W1[k][n]
// i < HV*HV/2      : build Wt2 word
__global__ void k_init(const float* __restrict__ W1, const float* __restrict__ W2) {
    int i = blockIdx.x * blockDim.x + threadIdx.x;
    if (i < NV) { g_out_deg[i] = 0; g_in_deg[i] = 0; g_cursor[i] = 0; }
    if (i < HV) { g_pooled[i] = 0.0f; g_pooled[HV + i] = __int_as_float(0xff800000); } // -inf
    if (i < HV * (FV / 2)) {
        int n  = i / (FV / 2);
        int kp = i % (FV / 2);
        __half2 h = __floats2half2_rn(W1[(size_t)(2 * kp) * HV + n],
                                      W1[(size_t)(2 * kp + 1) * HV + n]);
        g_wt1[i] = *(uint32_t*)&h;
    }
    if (i < HV * (HV / 2)) {
        int n  = i / (HV / 2);
        int kp = i % (HV / 2);
        __half2 h = __floats2half2_rn(W2[(size_t)(2 * kp) * HV + n],
                                      W2[(size_t)(2 * kp + 1) * HV + n]);
        g_wt2[i] = *(uint32_t*)&h;
    }
}

__global__ void k_deg(const int* __restrict__ src, const int* __restrict__ dst) {
    int e = blockIdx.x * blockDim.x + threadIdx.x;
    if (e < EV) {
        atomicAdd(&g_out_deg[src[e]], 1);
        atomicAdd(&g_in_deg[dst[e]], 1);
    }
}

__global__ void k_norm() {
    int i = blockIdx.x * blockDim.x + threadIdx.x;
    if (i < NV) {
        g_norm_src[i] = rsqrtf(fmaxf((float)g_out_deg[i], 1.0f));
        g_norm_dst[i] = rsqrtf(fmaxf((float)g_in_deg[i], 1.0f));
    }
}

// ---------------- exclusive scan of in_deg -> offsets (3 kernels) ----------------
__global__ void k_scan1() {
    __shared__ int s[256];
    int t = threadIdx.x;
    int i = blockIdx.x * 256 + t;
    int v = (i < NV) ? g_in_deg[i] : 0;
    s[t] = v;
    __syncthreads();
    #pragma unroll
    for (int off = 1; off < 256; off <<= 1) {
        int x = (t >= off) ? s[t - off] : 0;
        __syncthreads();
        s[t] += x;
        __syncthreads();
    }
    if (i < NV) g_offsets[i] = s[t] - v;
    if (t == 255) g_part[blockIdx.x] = s[255];
}

__global__ void k_scan2() {
    __shared__ int s[512];
    int t = threadIdx.x;
    int v = (t < NB_SCAN) ? g_part[t] : 0;
    s[t] = v;
    __syncthreads();
    #pragma unroll
    for (int off = 1; off < 512; off <<= 1) {
        int x = (t >= off) ? s[t - off] : 0;
        __syncthreads();
        s[t] += x;
        __syncthreads();
    }
    if (t < NB_SCAN) g_part[t] = s[t] - v;
}

__global__ void k_scan3() {
    int t = threadIdx.x;
    int i = blockIdx.x * 256 + t;
    if (i < NV) g_offsets[i] += g_part[blockIdx.x];
}

// ---------------- scatter edges into CSR-by-dst ----------------
__global__ void k_scatter(const int* __restrict__ src, const int* __restrict__ dst) {
    int e = blockIdx.x * blockDim.x + threadIdx.x;
    if (e < EV) {
        int d = dst[e];
        int p = atomicAdd(&g_cursor[d], 1);
        g_sorted_src[g_offsets[d] + p] = src[e];
    }
}

// ---------------- fp16 tensor-core GEMM (m16n8k16, fp32 accumulate) ----------------
// C[M,256] = ((A @ B) * norm_src[:,None]) stored fp16; A fp32 in gmem, B pre-transposed fp16.
// 128x128 block tile, 8 warps (4m x 2n), each 32x64. Double-buffered, 12-word smem row stride.
#define SRS 12   // smem row stride in 32-bit words (conflict-free for fragment reads)

__device__ __forceinline__ void mma_f16(float* c, const uint32_t* a, const uint32_t* b) {
    asm volatile(
        "mma.sync.aligned.m16n8k16.row.col.f32.f16.f16.f32 "
        "{%0,%1,%2,%3}, {%4,%5,%6,%7}, {%8,%9}, {%0,%1,%2,%3};"
        : "+f"(c[0]), "+f"(c[1]), "+f"(c[2]), "+f"(c[3])
        : "r"(a[0]), "r"(a[1]), "r"(a[2]), "r"(a[3]), "r"(b[0]), "r"(b[1]));
}

__global__ __launch_bounds__(256) void k_gemm_f16(const float* __restrict__ A,
                                                  const uint32_t* __restrict__ Wt,
                                                  __half* __restrict__ C,
                                                  int M, int K) {
    __shared__ uint32_t As[2][128 * SRS];   // [m][kp] packed fp16x2
    __shared__ uint32_t Bs[2][128 * SRS];   // [n][kp] packed fp16x2

    int tid  = threadIdx.x;
    int brow = blockIdx.y * 128;
    int bcol = blockIdx.x * 128;
    int Kp   = K >> 1;                      // K in fp16x2 words

    // ---- A-load mapping: row = tid/2, 8 k-values (2 float4) per thread ----
    int arow = tid >> 1;                    // 0..127
    int ahalf = tid & 1;                    // 0 -> k 0..7, 1 -> k 8..15
    int gr = brow + arow;
    bool v = gr < M;
    const float* Ap = A + (size_t)(v ? gr : 0) * K + ahalf * 8;

    // ---- B-load mapping: n = tid/2, one uint4 (8 halves = 8 k) per thread ----
    int bn = tid >> 1;
    int bhalf = tid & 1;
    const uint32_t* Bp = Wt + (size_t)(bcol + bn) * Kp + bhalf * 4;

    // ---- warp tiling: 8 warps (4m x 2n), each 32x64 ----
    int wid  = tid >> 5, lane = tid & 31;
    int wm = (wid & 3) * 32;
    int wn = (wid >> 2) * 64;
    int r  = lane >> 2;                     // 0..7
    int cq = lane & 3;                      // 0..3

    float acc[2][8][4];
    #pragma unroll
    for (int i = 0; i < 2; i++)
        #pragma unroll
        for (int j = 0; j < 8; j++)
            #pragma unroll
            for (int q = 0; q < 4; q++) acc[i][j][q] = 0.0f;

    // initial prefetch (k0 = 0)
    float4 pa0 = v ? *(const float4*)(Ap)     : make_float4(0,0,0,0);
    float4 pa1 = v ? *(const float4*)(Ap + 4) : make_float4(0,0,0,0);
    uint4  pbv = *(const uint4*)(Bp);

    int buf = 0;
    for (int k0 = 0; k0 < K; k0 += 16) {
        uint32_t* Asb = As[buf];
        uint32_t* Bsb = Bs[buf];
        // pack A to fp16x2 and store 4 contiguous words (16B aligned: 12*arow + 4*ahalf)
        {
            __half2 h0 = __floats2half2_rn(pa0.x, pa0.y);
            __half2 h1 = __floats2half2_rn(pa0.z, pa0.w);
            __half2 h2 = __floats2half2_rn(pa1.x, pa1.y);
            __half2 h3 = __floats2half2_rn(pa1.z, pa1.w);
            *(uint4*)&Asb[arow * SRS + ahalf * 4] =
                make_uint4(*(uint32_t*)&h0, *(uint32_t*)&h1, *(uint32_t*)&h2, *(uint32_t*)&h3);
            *(uint4*)&Bsb[bn * SRS + bhalf * 4] = pbv;
        }
        __syncthreads();

        int kn = k0 + 16;
        if (kn < K) {
            pa0 = v ? *(const float4*)(Ap + kn)     : make_float4(0,0,0,0);
            pa1 = v ? *(const float4*)(Ap + kn + 4) : make_float4(0,0,0,0);
            pbv = *(const uint4*)(Bp + (kn >> 1));
        }

        // one m16n8k16 step covers the whole 16-k tile
        uint32_t a[2][4], b[8][2];
        #pragma unroll
        for (int mt = 0; mt < 2; mt++) {
            int mbase = wm + mt * 16 + r;
            a[mt][0] = Asb[mbase * SRS + cq];            // A[r][2cq..+1]
            a[mt][1] = Asb[(mbase + 8) * SRS + cq];      // A[r+8][2cq..+1]
            a[mt][2] = Asb[mbase * SRS + cq + 4];        // A[r][2cq+8..+9]
            a[mt][3] = Asb[(mbase + 8) * SRS + cq + 4];  // A[r+8][2cq+8..+9]
        }
        #pragma unroll
        for (int nt = 0; nt < 8; nt++) {
            int nbase = wn + nt * 8 + r;
            b[nt][0] = Bsb[nbase * SRS + cq];            // B[2cq..+1][n]
            b[nt][1] = Bsb[nbase * SRS + cq + 4];        // B[2cq+8..+9][n]
        }
        #pragma unroll
        for (int mt = 0; mt < 2; mt++)
            #pragma unroll
            for (int nt = 0; nt < 8; nt++)
                mma_f16(acc[mt][nt], a[mt], b[nt]);

        buf ^= 1;
        __syncthreads();
    }

    // ---- epilogue: scale by norm_src[row], convert fp16 RN, store ----
    #pragma unroll
    for (int mt = 0; mt < 2; mt++) {
        int row0 = brow + wm + mt * 16 + r;
        int row1 = row0 + 8;
        float s0 = (row0 < M) ? g_norm_src[row0] : 0.0f;
        float s1 = (row1 < M) ? g_norm_src[row1] : 0.0f;
        #pragma unroll
        for (int nt = 0; nt < 8; nt++) {
            int col = bcol + wn + nt * 8 + cq * 2;
            if (row0 < M)
                *(__half2*)(C + (size_t)row0 * HV + col) =
                    __floats2half2_rn(acc[mt][nt][0] * s0, acc[mt][nt][1] * s0);
            if (row1 < M)
                *(__half2*)(C + (size_t)row1 * HV + col) =
                    __floats2half2_rn(acc[mt][nt][2] * s1, acc[mt][nt][3] * s1);
        }
    }
}

// ---------------- aggregation: h[n] = leaky( norm_dst[n]*sum_{e in CSR(n)} Y[src_e] + bias ) ----
__global__ void k_agg(const __half* __restrict__ Y, const float* __restrict__ bias,
                      float* __restrict__ O) {
    int node = blockIdx.x;
    int t = threadIdx.x;            // 0..63
    int start = g_offsets[node];
    int cnt   = g_in_deg[node];
    const uint2* Yv = (const uint2*)Y;   // row stride = 64 uint2

    float a0=0.f,a1=0.f,a2=0.f,a3=0.f;
    float b0=0.f,b1=0.f,b2=0.f,b3=0.f;
    float c0=0.f,c1=0.f,c2=0.f,c3=0.f;
    float d0=0.f,d1=0.f,d2=0.f,d3=0.f;
    int e = 0;
    for (; e + 4 <= cnt; e += 4) {
        int s0 = g_sorted_src[start + e];
        int s1 = g_sorted_src[start + e + 1];
        int s2 = g_sorted_src[start + e + 2];
        int s3 = g_sorted_src[start + e + 3];
        uint2 u0 = Yv[(size_t)s0 * 64 + t];
        uint2 u1 = Yv[(size_t)s1 * 64 + t];
        uint2 u2 = Yv[(size_t)s2 * 64 + t];
        uint2 u3 = Yv[(size_t)s3 * 64 + t];
        float2 x00 = __half22float2(*(__half2*)&u0.x), x01 = __half22float2(*(__half2*)&u0.y);
        float2 x10 = __half22float2(*(__half2*)&u1.x), x11 = __half22float2(*(__half2*)&u1.y);
        float2 x20 = __half22float2(*(__half2*)&u2.x), x21 = __half22float2(*(__half2*)&u2.y);
        float2 x30 = __half22float2(*(__half2*)&u3.x), x31 = __half22float2(*(__half2*)&u3.y);
        a0 += x00.x; a1 += x00.y; a2 += x01.x; a3 += x01.y;
        b0 += x10.x; b1 += x10.y; b2 += x11.x; b3 += x11.y;
        c0 += x20.x; c1 += x20.y; c2 += x21.x; c3 += x21.y;
        d0 += x30.x; d1 += x30.y; d2 += x31.x; d3 += x31.y;
    }
    for (; e < cnt; e++) {
        int s0 = g_sorted_src[start + e];
        uint2 u0 = Yv[(size_t)s0 * 64 + t];
        float2 x00 = __half22float2(*(__half2*)&u0.x), x01 = __half22float2(*(__half2*)&u0.y);
        a0 += x00.x; a1 += x00.y; a2 += x01.x; a3 += x01.y;
    }
    a0 += b0 + c0 + d0;
    a1 += b1 + c1 + d1;
    a2 += b2 + c2 + d2;
    a3 += b3 + c3 + d3;

    float nd = g_norm_dst[node];
    float4 bb = *(const float4*)(bias + t * 4);
    float4 o;
    o.x = a0 * nd + bb.x;  o.x = (o.x >= 0.0f) ? o.x : 0.01f * o.x;
    o.y = a1 * nd + bb.y;  o.y = (o.y >= 0.0f) ? o.y : 0.01f * o.y;
    o.z = a2 * nd + bb.z;  o.z = (o.z >= 0.0f) ? o.z : 0.01f * o.z;
    o.w = a3 * nd + bb.w;  o.w = (o.w >= 0.0f) ? o.w : 0.01f * o.w;
    *(float4*)(O + (size_t)node * HV + t * 4) = o;
}

// ---------------- pooling: column-wise sum and max of g_h ----------------
__device__ __forceinline__ void atomicMaxF(float* addr, float val) {
    int* ia = (int*)addr;
    int old = *ia;
    while (__int_as_float(old) < val) {
        int assumed = old;
        old = atomicCAS(ia, assumed, __float_as_int(val));
        if (old == assumed) break;
    }
}

__global__ void k_pool() {
    int t = threadIdx.x;  // 256
    float sum = 0.0f;
    float mx  = __int_as_float(0xff800000);
    for (int r = blockIdx.x; r < NV; r += gridDim.x) {
        float v = g_h[(size_t)r * HV + t];
        sum += v;
        mx = fmaxf(mx, v);
    }
    atomicAdd(&g_pooled[t], sum);
    atomicMaxF(&g_pooled[HV + t], mx);
}

__global__ void k_pick(const int* __restrict__ node_index) {
    int t = threadIdx.x;  // 256
    int ni = node_index[0];
    g_pooled[2 * HV + t] = g_h[(size_t)ni * HV + t];
}

// ---------------- head GEMV: fd[1024] = pooled[768] @ Wg[768,1024] + bg ----------------
__global__ void k_gemv(const float* __restrict__ Wg, const float* __restrict__ bg) {
    __shared__ float sp[3 * HV];
    int t = threadIdx.x;  // 256, grid 4
    for (int i = t; i < 3 * HV; i += 256) sp[i] = g_pooled[i];
    __syncthreads();
    int j = blockIdx.x * 256 + t;
    float acc = bg[j];
    #pragma unroll 8
    for (int k = 0; k < 3 * HV; k++) acc += sp[k] * Wg[(size_t)k * (2 * FV) + j];
    g_fd[j] = acc;
}

// ---------------- epilogue: reparam + log_prob ----------------
__global__ void k_final(const float* __restrict__ eps, float* __restrict__ out) {
    __shared__ float red[FV];
    int t = threadIdx.x;  // 512
    float mu = g_fd[t];
    float sg = fabsf(g_fd[FV + t]);
    float fn = mu + sg * eps[t];
    out[t]          = fn;
    out[FV + t]     = mu;
    out[2 * FV + t] = sg;
    float z = (fn - mu) / sg;
    const float half_log2pi = 0.9189385332046727f;
    float term = -0.5f * z * z - logf(sg) - half_log2pi;
    red[t] = term;
    __syncthreads();
    #pragma unroll
    for (int o = 256; o > 0; o >>= 1) {
        if (t < o) red[t] += red[t + o];
        __syncthreads();
    }
    if (t == 0) out[3 * FV] = red[0] / (float)FV;
}

// ---------------- launch ----------------
extern "C" void kernel_launch(void* const* d_in, const int* in_sizes, int n_in,
                              void* d_out, int out_size) {
    const float* feat       = (const float*)d_in[0];
    const int*   src        = (const int*)  d_in[1];
    const int*   dst        = (const int*)  d_in[2];
    const int*   node_index = (const int*)  d_in[3];
    const float* W1         = (const float*)d_in[4];
    const float* b1         = (const float*)d_in[5];
    const float* W2         = (const float*)d_in[6];
    const float* b2         = (const float*)d_in[7];
    const float* Wg         = (const float*)d_in[8];
    const float* bg         = (const float*)d_in[9];
    const float* eps        = (const float*)d_in[10];
    float*       out        = (float*)d_out;

    void *yp_v, *hp_v, *w1p_v, *w2p_v;
    cudaGetSymbolAddress(&yp_v, g_yh);
    cudaGetSymbolAddress(&hp_v, g_h);
    cudaGetSymbolAddress(&w1p_v, g_wt1);
    cudaGetSymbolAddress(&w2p_v, g_wt2);
    __half*   yp  = (__half*)yp_v;
    float*    hp  = (float*)hp_v;
    uint32_t* w1p = (uint32_t*)w1p_v;
    uint32_t* w2p = (uint32_t*)w2p_v;

    dim3 gemm_grid(1, (NV + 127) / 128);   // 128 N-cols covered per block? No: N=256 -> bcol grid 2
    dim3 gemm_grid2(2, (NV + 127) / 128);

    k_init<<<(NV + 255) / 256, 256>>>(W1, W2);
    k_deg<<<(EV + 255) / 256, 256>>>(src, dst);
    k_norm<<<(NV + 255) / 256, 256>>>();
    // GEMM1 at launch slot #4 for the fixed-index ncu capture
    k_gemm_f16<<<gemm_grid2, 256>>>(feat, w1p, yp, NV, FV);
    k_scan1<<<NB_SCAN, 256>>>();
    k_scan2<<<1, 512>>>();
    k_scan3<<<NB_SCAN, 256>>>();
    k_scatter<<<(EV + 255) / 256, 256>>>(src, dst);

    k_agg<<<NV, 64>>>(yp, b1, hp);
    k_gemm_f16<<<gemm_grid2, 256>>>(hp, w2p, yp, NV, HV);
    k_agg<<<NV, 64>>>(yp, b2, hp);

    k_pool<<<256, 256>>>();
    k_pick<<<1, 256>>>(node_index);
    k_gemv<<<4, 256>>>(Wg, bg);
    k_final<<<1, 512>>>(eps, out);
}

// round 8
// speedup vs baseline: 1.2854x; 1.0398x over previous
#include <cuda_runtime.h>
#include <cuda_fp16.h>
#include <cstdint>

// Problem constants (fixed by dataset)
#define NV 100000
#define EV 1600000
#define FV 512
#define HV 256
#define NB_SCAN ((NV + 255) / 256)   // 391

// ---------------- scratch (static device globals; no allocation) ----------------
__device__ int   g_out_deg[NV];
__device__ int   g_in_deg[NV];
__device__ float g_norm_src[NV];
__device__ float g_norm_dst[NV];
__device__ int   g_offsets[NV];
__device__ int   g_cursor[NV];
__device__ int   g_part[NB_SCAN];
__device__ int   g_sorted_src[EV];
__device__ __align__(16) __half g_yh[(size_t)NV * HV];  // pre-aggregation activations (fp16 RN)
__device__ __align__(16) float  g_h[(size_t)NV * HV];   // post-aggregation activations (fp32)
__device__ __align__(16) uint32_t g_wt1[HV * (FV / 2)]; // W1^T as fp16x2: [n][k/2]
__device__ __align__(16) uint32_t g_wt2[HV * (HV / 2)]; // W2^T as fp16x2
__device__ float g_pooled[3 * HV];
__device__ float g_fd[2 * FV];

// ---------------- init + degrees-zero + weight transpose/convert ----------------
__global__ void k_init(const float* __restrict__ W1, const float* __restrict__ W2) {
    int i = blockIdx.x * blockDim.x + threadIdx.x;
    if (i < NV) { g_out_deg[i] = 0; g_in_deg[i] = 0; g_cursor[i] = 0; }
    if (i < HV) { g_pooled[i] = 0.0f; g_pooled[HV + i] = __int_as_float(0xff800000); } // -inf
    if (i < HV * (FV / 2)) {
        int n  = i / (FV / 2);
        int kp = i % (FV / 2);
        __half2 h = __floats2half2_rn(W1[(size_t)(2 * kp) * HV + n],
                                      W1[(size_t)(2 * kp + 1) * HV + n]);
        g_wt1[i] = *(uint32_t*)&h;
    }
    if (i < HV * (HV / 2)) {
        int n  = i / (HV / 2);
        int kp = i % (HV / 2);
        __half2 h = __floats2half2_rn(W2[(size_t)(2 * kp) * HV + n],
                                      W2[(size_t)(2 * kp + 1) * HV + n]);
        g_wt2[i] = *(uint32_t*)&h;
    }
}

__global__ void k_deg(const int* __restrict__ src, const int* __restrict__ dst) {
    int e = blockIdx.x * blockDim.x + threadIdx.x;
    if (e < EV) {
        atomicAdd(&g_out_deg[src[e]], 1);
        atomicAdd(&g_in_deg[dst[e]], 1);
    }
}

__global__ void k_norm() {
    int i = blockIdx.x * blockDim.x + threadIdx.x;
    if (i < NV) {
        g_norm_src[i] = rsqrtf(fmaxf((float)g_out_deg[i], 1.0f));
        g_norm_dst[i] = rsqrtf(fmaxf((float)g_in_deg[i], 1.0f));
    }
}

// ---------------- exclusive scan of in_deg -> offsets ----------------
__global__ void k_scan1() {
    __shared__ int s[256];
    int t = threadIdx.x;
    int i = blockIdx.x * 256 + t;
    int v = (i < NV) ? g_in_deg[i] : 0;
    s[t] = v;
    __syncthreads();
    #pragma unroll
    for (int off = 1; off < 256; off <<= 1) {
        int x = (t >= off) ? s[t - off] : 0;
        __syncthreads();
        s[t] += x;
        __syncthreads();
    }
    if (i < NV) g_offsets[i] = s[t] - v;
    if (t == 255) g_part[blockIdx.x] = s[255];
}

__global__ void k_scan2() {
    __shared__ int s[512];
    int t = threadIdx.x;
    int v = (t < NB_SCAN) ? g_part[t] : 0;
    s[t] = v;
    __syncthreads();
    #pragma unroll
    for (int off = 1; off < 512; off <<= 1) {
        int x = (t >= off) ? s[t - off] : 0;
        __syncthreads();
        s[t] += x;
        __syncthreads();
    }
    if (t < NB_SCAN) g_part[t] = s[t] - v;
}

__global__ void k_scan3() {
    int t = threadIdx.x;
    int i = blockIdx.x * 256 + t;
    if (i < NV) g_offsets[i] += g_part[blockIdx.x];
}

// ---------------- scatter edges into CSR-by-dst ----------------
__global__ void k_scatter(const int* __restrict__ src, const int* __restrict__ dst) {
    int e = blockIdx.x * blockDim.x + threadIdx.x;
    if (e < EV) {
        int d = dst[e];
        int p = atomicAdd(&g_cursor[d], 1);
        g_sorted_src[g_offsets[d] + p] = src[e];
    }
}

// ---------------- fp16 tensor-core GEMM: ldmatrix fragments + cp.async B -----------
#define SRS 12   // smem row stride in 32-bit words

__device__ __forceinline__ void mma_f16(float* c, const uint32_t* a, const uint32_t* b) {
    asm volatile(
        "mma.sync.aligned.m16n8k16.row.col.f32.f16.f16.f32 "
        "{%0,%1,%2,%3}, {%4,%5,%6,%7}, {%8,%9}, {%0,%1,%2,%3};"
        : "+f"(c[0]), "+f"(c[1]), "+f"(c[2]), "+f"(c[3])
        : "r"(a[0]), "r"(a[1]), "r"(a[2]), "r"(a[3]), "r"(b[0]), "r"(b[1]));
}

__device__ __forceinline__ void ldsm_x4(uint32_t* r, uint32_t saddr) {
    asm volatile("ldmatrix.sync.aligned.m8n8.x4.shared.b16 {%0,%1,%2,%3}, [%4];"
                 : "=r"(r[0]), "=r"(r[1]), "=r"(r[2]), "=r"(r[3]) : "r"(saddr));
}

__device__ __forceinline__ void cp_async16(uint32_t dst, const void* src) {
    asm volatile("cp.async.ca.shared.global [%0], [%1], 16;" :: "r"(dst), "l"(src) : "memory");
}

__global__ __launch_bounds__(256) void k_gemm_f16(const float* __restrict__ A,
                                                  const uint32_t* __restrict__ Wt,
                                                  __half* __restrict__ C,
                                                  int M, int K) {
    __shared__ uint32_t As[2][128 * SRS];   // [m][kp] packed fp16x2
    __shared__ uint32_t Bs[2][128 * SRS];   // [n][kp] packed fp16x2

    int tid  = threadIdx.x;
    int brow = blockIdx.y * 128;
    int bcol = blockIdx.x * 128;
    int Kp   = K >> 1;

    uint32_t as_base = (uint32_t)__cvta_generic_to_shared(&As[0][0]);
    uint32_t bs_base = (uint32_t)__cvta_generic_to_shared(&Bs[0][0]);
    const uint32_t BUFB = 128 * SRS * 4;    // bytes per buffer

    // ---- A-load mapping: row = tid/2, 8 k-values per thread ----
    int arow = tid >> 1;
    int ahalf = tid & 1;
    int gr = brow + arow;
    bool v = gr < M;
    const float* Ap = A + (size_t)(v ? gr : 0) * K + ahalf * 8;
    uint32_t a_st = as_base + (arow * SRS + ahalf * 4) * 4;

    // ---- B cp.async mapping: n = tid/2, 16B (8 k-halves) per thread ----
    int bn = tid >> 1;
    int bhalf = tid & 1;
    const uint32_t* Bp = Wt + (size_t)(bcol + bn) * Kp + bhalf * 4;
    uint32_t b_st = bs_base + (bn * SRS + bhalf * 4) * 4;

    // ---- warp tiling: 8 warps (4m x 2n), each 32x64 ----
    int wid  = tid >> 5, lane = tid & 31;
    int wm = (wid & 3) * 32;
    int wn = (wid >> 2) * 64;
    int r  = lane >> 2;
    int cq = lane & 3;

    // ldmatrix source addresses (byte offsets inside a buffer)
    // A: x4 over 16 rows x 16 halves: lanes 0-7 rows 0-7 k-lo, 8-15 rows 8-15 k-lo,
    //    16-23 rows 0-7 k-hi, 24-31 rows 8-15 k-hi
    uint32_t a_ld_off0 = ((wm + (lane & 15)) * SRS + (lane >> 4) * 4) * 4;
    uint32_t a_ld_off1 = ((wm + 16 + (lane & 15)) * SRS + (lane >> 4) * 4) * 4;
    // B: x4 over 16 n-rows x 16 halves: lanes 0-7 n 0-7 k-lo, 8-15 n 0-7 k-hi,
    //    16-23 n 8-15 k-lo, 24-31 n 8-15 k-hi
    int bn_in = (lane & 7) + ((lane >> 4) << 3);
    int bk_in = (lane >> 3) & 1;
    uint32_t b_ld_off[4];
    #pragma unroll
    for (int j = 0; j < 4; j++)
        b_ld_off[j] = ((wn + j * 16 + bn_in) * SRS + bk_in * 4) * 4;

    float acc[2][8][4];
    #pragma unroll
    for (int i = 0; i < 2; i++)
        #pragma unroll
        for (int j = 0; j < 8; j++)
            #pragma unroll
            for (int q = 0; q < 4; q++) acc[i][j][q] = 0.0f;

    // prologue: A(0) to regs, B(0) via cp.async into buf 0
    float4 pa0 = v ? *(const float4*)(Ap)     : make_float4(0,0,0,0);
    float4 pa1 = v ? *(const float4*)(Ap + 4) : make_float4(0,0,0,0);
    cp_async16(b_st, Bp);
    asm volatile("cp.async.commit_group;" ::: "memory");

    int buf = 0;
    for (int k0 = 0; k0 < K; k0 += 16) {
        // store A(k0) (cvt to fp16) into As[buf]
        {
            __half2 h0 = __floats2half2_rn(pa0.x, pa0.y);
            __half2 h1 = __floats2half2_rn(pa0.z, pa0.w);
            __half2 h2 = __floats2half2_rn(pa1.x, pa1.y);
            __half2 h3 = __floats2half2_rn(pa1.z, pa1.w);
            uint4 w = make_uint4(*(uint32_t*)&h0, *(uint32_t*)&h1,
                                 *(uint32_t*)&h2, *(uint32_t*)&h3);
            asm volatile("st.shared.v4.b32 [%0], {%1,%2,%3,%4};"
                         :: "r"(a_st + buf * BUFB), "r"(w.x), "r"(w.y), "r"(w.z), "r"(w.w)
                         : "memory");
        }

        int kn = k0 + 16;
        if (kn < K) {
            // prefetch A(k+1) into regs; issue B(k+1) into buf^1
            pa0 = v ? *(const float4*)(Ap + kn)     : make_float4(0,0,0,0);
            pa1 = v ? *(const float4*)(Ap + kn + 4) : make_float4(0,0,0,0);
            cp_async16(b_st + (buf ^ 1) * BUFB, Bp + (kn >> 1));
            asm volatile("cp.async.commit_group;" ::: "memory");
            asm volatile("cp.async.wait_group 1;" ::: "memory");   // B(k0) resident
        } else {
            asm volatile("cp.async.wait_group 0;" ::: "memory");
        }
        __syncthreads();

        // fragments via ldmatrix
        uint32_t a[2][4], b[8][2];
        uint32_t abase = as_base + buf * BUFB;
        uint32_t bbase = bs_base + buf * BUFB;
        ldsm_x4(a[0], abase + a_ld_off0);
        ldsm_x4(a[1], abase + a_ld_off1);
        #pragma unroll
        for (int j = 0; j < 4; j++) {
            uint32_t rr[4];
            ldsm_x4(rr, bbase + b_ld_off[j]);
            b[2*j][0]   = rr[0];
            b[2*j][1]   = rr[1];
            b[2*j+1][0] = rr[2];
            b[2*j+1][1] = rr[3];
        }
        #pragma unroll
        for (int mt = 0; mt < 2; mt++)
            #pragma unroll
            for (int nt = 0; nt < 8; nt++)
                mma_f16(acc[mt][nt], a[mt], b[nt]);

        buf ^= 1;
        __syncthreads();
    }

    // ---- epilogue: scale by norm_src[row], convert fp16 RN, store ----
    #pragma unroll
    for (int mt = 0; mt < 2; mt++) {
        int row0 = brow + wm + mt * 16 + r;
        int row1 = row0 + 8;
        float s0 = (row0 < M) ? g_norm_src[row0] : 0.0f;
        float s1 = (row1 < M) ? g_norm_src[row1] : 0.0f;
        #pragma unroll
        for (int nt = 0; nt < 8; nt++) {
            int col = bcol + wn + nt * 8 + cq * 2;
            if (row0 < M)
                *(__half2*)(C + (size_t)row0 * HV + col) =
                    __floats2half2_rn(acc[mt][nt][0] * s0, acc[mt][nt][1] * s0);
            if (row1 < M)
                *(__half2*)(C + (size_t)row1 * HV + col) =
                    __floats2half2_rn(acc[mt][nt][2] * s1, acc[mt][nt][3] * s1);
        }
    }
}

// ---------------- aggregation: h[n] = leaky( norm_dst[n]*sum_{e in CSR(n)} Y[src_e] + bias ) ----
__global__ void k_agg(const __half* __restrict__ Y, const float* __restrict__ bias,
                      float* __restrict__ O) {
    int node = blockIdx.x;
    int t = threadIdx.x;            // 0..63
    int start = g_offsets[node];
    int cnt   = g_in_deg[node];
    const uint2* Yv = (const uint2*)Y;

    float a0=0.f,a1=0.f,a2=0.f,a3=0.f;
    float b0=0.f,b1=0.f,b2=0.f,b3=0.f;
    float c0=0.f,c1=0.f,c2=0.f,c3=0.f;
    float d0=0.f,d1=0.f,d2=0.f,d3=0.f;
    int e = 0;
    for (; e + 4 <= cnt; e += 4) {
        int s0 = g_sorted_src[start + e];
        int s1 = g_sorted_src[start + e + 1];
        int s2 = g_sorted_src[start + e + 2];
        int s3 = g_sorted_src[start + e + 3];
        uint2 u0 = Yv[(size_t)s0 * 64 + t];
        uint2 u1 = Yv[(size_t)s1 * 64 + t];
        uint2 u2 = Yv[(size_t)s2 * 64 + t];
        uint2 u3 = Yv[(size_t)s3 * 64 + t];
        float2 x00 = __half22float2(*(__half2*)&u0.x), x01 = __half22float2(*(__half2*)&u0.y);
        float2 x10 = __half22float2(*(__half2*)&u1.x), x11 = __half22float2(*(__half2*)&u1.y);
        float2 x20 = __half22float2(*(__half2*)&u2.x), x21 = __half22float2(*(__half2*)&u2.y);
        float2 x30 = __half22float2(*(__half2*)&u3.x), x31 = __half22float2(*(__half2*)&u3.y);
        a0 += x00.x; a1 += x00.y; a2 += x01.x; a3 += x01.y;
        b0 += x10.x; b1 += x10.y; b2 += x11.x; b3 += x11.y;
        c0 += x20.x; c1 += x20.y; c2 += x21.x; c3 += x21.y;
        d0 += x30.x; d1 += x30.y; d2 += x31.x; d3 += x31.y;
    }
    for (; e < cnt; e++) {
        int s0 = g_sorted_src[start + e];
        uint2 u0 = Yv[(size_t)s0 * 64 + t];
        float2 x00 = __half22float2(*(__half2*)&u0.x), x01 = __half22float2(*(__half2*)&u0.y);
        a0 += x00.x; a1 += x00.y; a2 += x01.x; a3 += x01.y;
    }
    a0 += b0 + c0 + d0;
    a1 += b1 + c1 + d1;
    a2 += b2 + c2 + d2;
    a3 += b3 + c3 + d3;

    float nd = g_norm_dst[node];
    float4 bb = *(const float4*)(bias + t * 4);
    float4 o;
    o.x = a0 * nd + bb.x;  o.x = (o.x >= 0.0f) ? o.x : 0.01f * o.x;
    o.y = a1 * nd + bb.y;  o.y = (o.y >= 0.0f) ? o.y : 0.01f * o.y;
    o.z = a2 * nd + bb.z;  o.z = (o.z >= 0.0f) ? o.z : 0.01f * o.z;
    o.w = a3 * nd + bb.w;  o.w = (o.w >= 0.0f) ? o.w : 0.01f * o.w;
    *(float4*)(O + (size_t)node * HV + t * 4) = o;
}

// ---------------- pooling ----------------
__device__ __forceinline__ void atomicMaxF(float* addr, float val) {
    int* ia = (int*)addr;
    int old = *ia;
    while (__int_as_float(old) < val) {
        int assumed = old;
        old = atomicCAS(ia, assumed, __float_as_int(val));
        if (old == assumed) break;
    }
}

__global__ void k_pool() {
    int t = threadIdx.x;  // 256
    float sum = 0.0f;
    float mx  = __int_as_float(0xff800000);
    for (int r = blockIdx.x; r < NV; r += gridDim.x) {
        float v = g_h[(size_t)r * HV + t];
        sum += v;
        mx = fmaxf(mx, v);
    }
    atomicAdd(&g_pooled[t], sum);
    atomicMaxF(&g_pooled[HV + t], mx);
}

__global__ void k_pick(const int* __restrict__ node_index) {
    int t = threadIdx.x;  // 256
    int ni = node_index[0];
    g_pooled[2 * HV + t] = g_h[(size_t)ni * HV + t];
}

// ---------------- head GEMV ----------------
__global__ void k_gemv(const float* __restrict__ Wg, const float* __restrict__ bg) {
    __shared__ float sp[3 * HV];
    int t = threadIdx.x;  // 256, grid 4
    for (int i = t; i < 3 * HV; i += 256) sp[i] = g_pooled[i];
    __syncthreads();
    int j = blockIdx.x * 256 + t;
    float acc = bg[j];
    #pragma unroll 8
    for (int k = 0; k < 3 * HV; k++) acc += sp[k] * Wg[(size_t)k * (2 * FV) + j];
    g_fd[j] = acc;
}

// ---------------- epilogue: reparam + log_prob ----------------
__global__ void k_final(const float* __restrict__ eps, float* __restrict__ out) {
    __shared__ float red[FV];
    int t = threadIdx.x;  // 512
    float mu = g_fd[t];
    float sg = fabsf(g_fd[FV + t]);
    float fn = mu + sg * eps[t];
    out[t]          = fn;
    out[FV + t]     = mu;
    out[2 * FV + t] = sg;
    float z = (fn - mu) / sg;
    const float half_log2pi = 0.9189385332046727f;
    float term = -0.5f * z * z - logf(sg) - half_log2pi;
    red[t] = term;
    __syncthreads();
    #pragma unroll
    for (int o = 256; o > 0; o >>= 1) {
        if (t < o) red[t] += red[t + o];
        __syncthreads();
    }
    if (t == 0) out[3 * FV] = red[0] / (float)FV;
}

// ---------------- launch ----------------
extern "C" void kernel_launch(void* const* d_in, const int* in_sizes, int n_in,
                              void* d_out, int out_size) {
    const float* feat       = (const float*)d_in[0];
    const int*   src        = (const int*)  d_in[1];
    const int*   dst        = (const int*)  d_in[2];
    const int*   node_index = (const int*)  d_in[3];
    const float* W1         = (const float*)d_in[4];
    const float* b1         = (const float*)d_in[5];
    const float* W2         = (const float*)d_in[6];
    const float* b2         = (const float*)d_in[7];
    const float* Wg         = (const float*)d_in[8];
    const float* bg         = (const float*)d_in[9];
    const float* eps        = (const float*)d_in[10];
    float*       out        = (float*)d_out;

    void *yp_v, *hp_v, *w1p_v, *w2p_v;
    cudaGetSymbolAddress(&yp_v, g_yh);
    cudaGetSymbolAddress(&hp_v, g_h);
    cudaGetSymbolAddress(&w1p_v, g_wt1);
    cudaGetSymbolAddress(&w2p_v, g_wt2);
    __half*   yp  = (__half*)yp_v;
    float*    hp  = (float*)hp_v;
    uint32_t* w1p = (uint32_t*)w1p_v;
    uint32_t* w2p = (uint32_t*)w2p_v;

    dim3 gemm_grid(2, (NV + 127) / 128);

    k_init<<<(NV + 255) / 256, 256>>>(W1, W2);
    k_deg<<<(EV + 255) / 256, 256>>>(src, dst);
    k_norm<<<(NV + 255) / 256, 256>>>();
    // GEMM1 at launch slot #4 for the fixed-index ncu capture
    k_gemm_f16<<<gemm_grid, 256>>>(feat, w1p, yp, NV, FV);
    k_scan1<<<NB_SCAN, 256>>>();
    k_scan2<<<1, 512>>>();
    k_scan3<<<NB_SCAN, 256>>>();
    k_scatter<<<(EV + 255) / 256, 256>>>(src, dst);

    k_agg<<<NV, 64>>>(yp, b1, hp);
    k_gemm_f16<<<gemm_grid, 256>>>(hp, w2p, yp, NV, HV);
    k_agg<<<NV, 64>>>(yp, b2, hp);

    k_pool<<<256, 256>>>();
    k_pick<<<1, 256>>>(node_index);
    k_gemv<<<4, 256>>>(Wg, bg);
    k_final<<<1, 512>>>(eps, out);
}

// round 9
// speedup vs baseline: 1.3714x; 1.0669x over previous
#include <cuda_runtime.h>
#include <cuda_fp16.h>
#include <cstdint>

// Problem constants (fixed by dataset)
#define NV 100000
#define EV 1600000
#define FV 512
#define HV 256
#define NB_SCAN ((NV + 255) / 256)   // 391

// ---------------- scratch (static device globals; no allocation) ----------------
__device__ int   g_out_deg[NV];
__device__ int   g_in_deg[NV];
__device__ float g_norm_src[NV];
__device__ float g_norm_dst[NV];
__device__ int   g_offsets[NV];
__device__ int   g_cursor[NV];
__device__ int   g_part[NB_SCAN];
__device__ int   g_sorted_src[EV];
__device__ __align__(16) __half g_yh[(size_t)NV * HV];  // pre-aggregation activations (fp16)
__device__ __align__(16) __half g_hh[(size_t)NV * HV];  // post-aggregation activations (fp16)
__device__ __align__(16) uint32_t g_wt1[HV * (FV / 2)]; // W1^T as fp16x2: [n][k/2]
__device__ __align__(16) uint32_t g_wt2[HV * (HV / 2)]; // W2^T as fp16x2
__device__ float g_pooled[3 * HV];
__device__ float g_fd[2 * FV];

// ---------------- init + degrees-zero + weight transpose/convert ----------------
__global__ void k_init(const float* __restrict__ W1, const float* __restrict__ W2) {
    int i = blockIdx.x * blockDim.x + threadIdx.x;
    if (i < NV) { g_out_deg[i] = 0; g_in_deg[i] = 0; g_cursor[i] = 0; }
    if (i < HV) { g_pooled[i] = 0.0f; g_pooled[HV + i] = __int_as_float(0xff800000); } // -inf
    if (i < HV * (FV / 2)) {
        int n  = i / (FV / 2);
        int kp = i % (FV / 2);
        __half2 h = __floats2half2_rn(W1[(size_t)(2 * kp) * HV + n],
                                      W1[(size_t)(2 * kp + 1) * HV + n]);
        g_wt1[i] = *(uint32_t*)&h;
    }
    if (i < HV * (HV / 2)) {
        int n  = i / (HV / 2);
        int kp = i % (HV / 2);
        __half2 h = __floats2half2_rn(W2[(size_t)(2 * kp) * HV + n],
                                      W2[(size_t)(2 * kp + 1) * HV + n]);
        g_wt2[i] = *(uint32_t*)&h;
    }
}

__global__ void k_deg(const int* __restrict__ src, const int* __restrict__ dst) {
    int e = blockIdx.x * blockDim.x + threadIdx.x;
    if (e < EV) {
        atomicAdd(&g_out_deg[src[e]], 1);
        atomicAdd(&g_in_deg[dst[e]], 1);
    }
}

__global__ void k_norm() {
    int i = blockIdx.x * blockDim.x + threadIdx.x;
    if (i < NV) {
        g_norm_src[i] = rsqrtf(fmaxf((float)g_out_deg[i], 1.0f));
        g_norm_dst[i] = rsqrtf(fmaxf((float)g_in_deg[i], 1.0f));
    }
}

// ---------------- exclusive scan of in_deg -> offsets ----------------
__global__ void k_scan1() {
    __shared__ int s[256];
    int t = threadIdx.x;
    int i = blockIdx.x * 256 + t;
    int v = (i < NV) ? g_in_deg[i] : 0;
    s[t] = v;
    __syncthreads();
    #pragma unroll
    for (int off = 1; off < 256; off <<= 1) {
        int x = (t >= off) ? s[t - off] : 0;
        __syncthreads();
        s[t] += x;
        __syncthreads();
    }
    if (i < NV) g_offsets[i] = s[t] - v;
    if (t == 255) g_part[blockIdx.x] = s[255];
}

__global__ void k_scan2() {
    __shared__ int s[512];
    int t = threadIdx.x;
    int v = (t < NB_SCAN) ? g_part[t] : 0;
    s[t] = v;
    __syncthreads();
    #pragma unroll
    for (int off = 1; off < 512; off <<= 1) {
        int x = (t >= off) ? s[t - off] : 0;
        __syncthreads();
        s[t] += x;
        __syncthreads();
    }
    if (t < NB_SCAN) g_part[t] = s[t] - v;
}

__global__ void k_scan3() {
    int t = threadIdx.x;
    int i = blockIdx.x * 256 + t;
    if (i < NV) g_offsets[i] += g_part[blockIdx.x];
}

// ---------------- scatter edges into CSR-by-dst ----------------
__global__ void k_scatter(const int* __restrict__ src, const int* __restrict__ dst) {
    int e = blockIdx.x * blockDim.x + threadIdx.x;
    if (e < EV) {
        int d = dst[e];
        int p = atomicAdd(&g_cursor[d], 1);
        g_sorted_src[g_offsets[d] + p] = src[e];
    }
}

// ---------------- fp16 mma GEMM: BK=32, single sync/tile, ldmatrix + cp.async B ----
#define SRS2 20   // smem row stride in 32-bit words (16 data + 4 pad; ldsm conflict-free)

__device__ __forceinline__ void mma_f16(float* c, const uint32_t* a, const uint32_t* b) {
    asm volatile(
        "mma.sync.aligned.m16n8k16.row.col.f32.f16.f16.f32 "
        "{%0,%1,%2,%3}, {%4,%5,%6,%7}, {%8,%9}, {%0,%1,%2,%3};"
        : "+f"(c[0]), "+f"(c[1]), "+f"(c[2]), "+f"(c[3])
        : "r"(a[0]), "r"(a[1]), "r"(a[2]), "r"(a[3]), "r"(b[0]), "r"(b[1]));
}

__device__ __forceinline__ void ldsm_x4(uint32_t* r, uint32_t saddr) {
    asm volatile("ldmatrix.sync.aligned.m8n8.x4.shared.b16 {%0,%1,%2,%3}, [%4];"
                 : "=r"(r[0]), "=r"(r[1]), "=r"(r[2]), "=r"(r[3]) : "r"(saddr));
}

__device__ __forceinline__ void cp_async16(uint32_t dst, const void* src) {
    asm volatile("cp.async.ca.shared.global [%0], [%1], 16;" :: "r"(dst), "l"(src) : "memory");
}

__device__ __forceinline__ void sts_v4(uint32_t addr, uint4 w) {
    asm volatile("st.shared.v4.b32 [%0], {%1,%2,%3,%4};"
                 :: "r"(addr), "r"(w.x), "r"(w.y), "r"(w.z), "r"(w.w) : "memory");
}

template <bool AHALF>
__global__ __launch_bounds__(256, 2) void k_gemm(const float*  __restrict__ Af,
                                                 const __half* __restrict__ Ah,
                                                 const uint32_t* __restrict__ Wt,
                                                 __half* __restrict__ C,
                                                 int M, int K) {
    __shared__ uint32_t As[2][128 * SRS2];   // [m][kp 0..15] packed fp16x2
    __shared__ uint32_t Bs[2][128 * SRS2];   // [n][kp 0..15]

    int tid  = threadIdx.x;
    int brow = blockIdx.y * 128;
    int bcol = blockIdx.x * 128;
    int Kp   = K >> 1;                       // K in fp16x2 words

    uint32_t as_base = (uint32_t)__cvta_generic_to_shared(&As[0][0]);
    uint32_t bs_base = (uint32_t)__cvta_generic_to_shared(&Bs[0][0]);
    const uint32_t BUFB = 128 * SRS2 * 4;    // bytes per buffer

    // ---- A-load mapping: row = tid/2, 16 k-values (halves of 32) per thread ----
    int arow  = tid >> 1;
    int ahalf = tid & 1;                     // 0: k 0..15 of tile, 1: k 16..31
    int gr = brow + arow;
    bool v = gr < M;
    const float*    Apf = Af ? (Af + (size_t)(v ? gr : 0) * K  + ahalf * 16) : nullptr;
    const uint32_t* Aph = Ah ? ((const uint32_t*)Ah + (size_t)(v ? gr : 0) * Kp + ahalf * 8) : nullptr;
    uint32_t a_st = as_base + (arow * SRS2 + ahalf * 8) * 4;

    // ---- B cp.async mapping: n = tid/2, 32B (16 k-halves) per thread (2x16B) ----
    int bn    = tid >> 1;
    int bhalf = tid & 1;
    const uint32_t* Bp = Wt + (size_t)(bcol + bn) * Kp + bhalf * 8;
    uint32_t b_st = bs_base + (bn * SRS2 + bhalf * 8) * 4;

    // ---- warp tiling: 8 warps (4m x 2n), each 32x64 ----
    int wid  = tid >> 5, lane = tid & 31;
    int wm = (wid & 3) * 32;
    int wn = (wid >> 2) * 64;
    int r  = lane >> 2;
    int cq = lane & 3;

    // ldmatrix byte offsets within a buffer (ks adds 32B = 8 words)
    uint32_t a_ld_off0 = ((wm + (lane & 15)) * SRS2 + (lane >> 4) * 4) * 4;
    uint32_t a_ld_off1 = ((wm + 16 + (lane & 15)) * SRS2 + (lane >> 4) * 4) * 4;
    int bn_in = (lane & 7) + ((lane >> 4) << 3);
    int bk_in = (lane >> 3) & 1;
    uint32_t b_ld_off[4];
    #pragma unroll
    for (int j = 0; j < 4; j++)
        b_ld_off[j] = ((wn + j * 16 + bn_in) * SRS2 + bk_in * 4) * 4;

    float acc[2][8][4];
    #pragma unroll
    for (int i = 0; i < 2; i++)
        #pragma unroll
        for (int j = 0; j < 8; j++)
            #pragma unroll
            for (int q = 0; q < 4; q++) acc[i][j][q] = 0.0f;

    // prefetch registers
    float4 pa[4];
    uint4  qa[2];

    // prologue: A(0) -> regs, B(0) -> buf0 via cp.async
    if (AHALF) {
        qa[0] = v ? *(const uint4*)(Aph)     : make_uint4(0,0,0,0);
        qa[1] = v ? *(const uint4*)(Aph + 4) : make_uint4(0,0,0,0);
    } else {
        #pragma unroll
        for (int i = 0; i < 4; i++)
            pa[i] = v ? *(const float4*)(Apf + i * 4) : make_float4(0,0,0,0);
    }
    cp_async16(b_st,      Bp);
    cp_async16(b_st + 16, Bp + 4);
    asm volatile("cp.async.commit_group;" ::: "memory");

    int buf = 0;
    for (int k0 = 0; k0 < K; k0 += 32) {
        // store A(k0) into As[buf]
        uint32_t ast = a_st + buf * BUFB;
        if (AHALF) {
            sts_v4(ast,      qa[0]);
            sts_v4(ast + 16, qa[1]);
        } else {
            __half2 h0 = __floats2half2_rn(pa[0].x, pa[0].y);
            __half2 h1 = __floats2half2_rn(pa[0].z, pa[0].w);
            __half2 h2 = __floats2half2_rn(pa[1].x, pa[1].y);
            __half2 h3 = __floats2half2_rn(pa[1].z, pa[1].w);
            __half2 h4 = __floats2half2_rn(pa[2].x, pa[2].y);
            __half2 h5 = __floats2half2_rn(pa[2].z, pa[2].w);
            __half2 h6 = __floats2half2_rn(pa[3].x, pa[3].y);
            __half2 h7 = __floats2half2_rn(pa[3].z, pa[3].w);
            sts_v4(ast,      make_uint4(*(uint32_t*)&h0, *(uint32_t*)&h1, *(uint32_t*)&h2, *(uint32_t*)&h3));
            sts_v4(ast + 16, make_uint4(*(uint32_t*)&h4, *(uint32_t*)&h5, *(uint32_t*)&h6, *(uint32_t*)&h7));
        }

        asm volatile("cp.async.wait_group 0;" ::: "memory");   // B(k0) landed
        __syncthreads();                                       // single barrier per tile

        int kn = k0 + 32;
        if (kn < K) {
            // prefetch A(kn) into regs; issue B(kn) into buf^1 (safe: after the sync)
            if (AHALF) {
                qa[0] = v ? *(const uint4*)(Aph + (kn >> 1))     : make_uint4(0,0,0,0);
                qa[1] = v ? *(const uint4*)(Aph + (kn >> 1) + 4) : make_uint4(0,0,0,0);
            } else {
                #pragma unroll
                for (int i = 0; i < 4; i++)
                    pa[i] = v ? *(const float4*)(Apf + kn + i * 4) : make_float4(0,0,0,0);
            }
            uint32_t bdst = b_st + (buf ^ 1) * BUFB;
            cp_async16(bdst,      Bp + (kn >> 1));
            cp_async16(bdst + 16, Bp + (kn >> 1) + 4);
            asm volatile("cp.async.commit_group;" ::: "memory");
        }

        // compute: 2 k-steps of m16n8k16
        uint32_t abase = as_base + buf * BUFB;
        uint32_t bbase = bs_base + buf * BUFB;
        #pragma unroll
        for (int ks = 0; ks < 2; ks++) {
            uint32_t koff = ks * 32;   // 8 words
            uint32_t a[2][4], b[8][2];
            ldsm_x4(a[0], abase + a_ld_off0 + koff);
            ldsm_x4(a[1], abase + a_ld_off1 + koff);
            #pragma unroll
            for (int j = 0; j < 4; j++) {
                uint32_t rr[4];
                ldsm_x4(rr, bbase + b_ld_off[j] + koff);
                b[2*j][0]   = rr[0];
                b[2*j][1]   = rr[1];
                b[2*j+1][0] = rr[2];
                b[2*j+1][1] = rr[3];
            }
            #pragma unroll
            for (int mt = 0; mt < 2; mt++)
                #pragma unroll
                for (int nt = 0; nt < 8; nt++)
                    mma_f16(acc[mt][nt], a[mt], b[nt]);
        }
        buf ^= 1;
        // no second __syncthreads(): next store targets buf^1, last read 2 iters ago
    }

    // ---- epilogue: scale by norm_src[row], convert fp16 RN, store ----
    #pragma unroll
    for (int mt = 0; mt < 2; mt++) {
        int row0 = brow + wm + mt * 16 + r;
        int row1 = row0 + 8;
        float s0 = (row0 < M) ? g_norm_src[row0] : 0.0f;
        float s1 = (row1 < M) ? g_norm_src[row1] : 0.0f;
        #pragma unroll
        for (int nt = 0; nt < 8; nt++) {
            int col = bcol + wn + nt * 8 + cq * 2;
            if (row0 < M)
                *(__half2*)(C + (size_t)row0 * HV + col) =
                    __floats2half2_rn(acc[mt][nt][0] * s0, acc[mt][nt][1] * s0);
            if (row1 < M)
                *(__half2*)(C + (size_t)row1 * HV + col) =
                    __floats2half2_rn(acc[mt][nt][2] * s1, acc[mt][nt][3] * s1);
        }
    }
}

// ---------------- aggregation: h[n] = leaky( norm_dst[n]*sum Y[src_e] + bias ), fp16 out ----
__global__ void k_agg(const __half* __restrict__ Y, const float* __restrict__ bias,
                      __half* __restrict__ O) {
    int node = blockIdx.x;
    int t = threadIdx.x;            // 0..63
    int start = g_offsets[node];
    int cnt   = g_in_deg[node];
    const uint2* Yv = (const uint2*)Y;

    float a0=0.f,a1=0.f,a2=0.f,a3=0.f;
    float b0=0.f,b1=0.f,b2=0.f,b3=0.f;
    float c0=0.f,c1=0.f,c2=0.f,c3=0.f;
    float d0=0.f,d1=0.f,d2=0.f,d3=0.f;
    int e = 0;
    for (; e + 4 <= cnt; e += 4) {
        int s0 = g_sorted_src[start + e];
        int s1 = g_sorted_src[start + e + 1];
        int s2 = g_sorted_src[start + e + 2];
        int s3 = g_sorted_src[start + e + 3];
        uint2 u0 = Yv[(size_t)s0 * 64 + t];
        uint2 u1 = Yv[(size_t)s1 * 64 + t];
        uint2 u2 = Yv[(size_t)s2 * 64 + t];
        uint2 u3 = Yv[(size_t)s3 * 64 + t];
        float2 x00 = __half22float2(*(__half2*)&u0.x), x01 = __half22float2(*(__half2*)&u0.y);
        float2 x10 = __half22float2(*(__half2*)&u1.x), x11 = __half22float2(*(__half2*)&u1.y);
        float2 x20 = __half22float2(*(__half2*)&u2.x), x21 = __half22float2(*(__half2*)&u2.y);
        float2 x30 = __half22float2(*(__half2*)&u3.x), x31 = __half22float2(*(__half2*)&u3.y);
        a0 += x00.x; a1 += x00.y; a2 += x01.x; a3 += x01.y;
        b0 += x10.x; b1 += x10.y; b2 += x11.x; b3 += x11.y;
        c0 += x20.x; c1 += x20.y; c2 += x21.x; c3 += x21.y;
        d0 += x30.x; d1 += x30.y; d2 += x31.x; d3 += x31.y;
    }
    for (; e < cnt; e++) {
        int s0 = g_sorted_src[start + e];
        uint2 u0 = Yv[(size_t)s0 * 64 + t];
        float2 x00 = __half22float2(*(__half2*)&u0.x), x01 = __half22float2(*(__half2*)&u0.y);
        a0 += x00.x; a1 += x00.y; a2 += x01.x; a3 += x01.y;
    }
    a0 += b0 + c0 + d0;
    a1 += b1 + c1 + d1;
    a2 += b2 + c2 + d2;
    a3 += b3 + c3 + d3;

    float nd = g_norm_dst[node];
    float4 bb = *(const float4*)(bias + t * 4);
    float o0 = a0 * nd + bb.x;  o0 = (o0 >= 0.0f) ? o0 : 0.01f * o0;
    float o1 = a1 * nd + bb.y;  o1 = (o1 >= 0.0f) ? o1 : 0.01f * o1;
    float o2 = a2 * nd + bb.z;  o2 = (o2 >= 0.0f) ? o2 : 0.01f * o2;
    float o3 = a3 * nd + bb.w;  o3 = (o3 >= 0.0f) ? o3 : 0.01f * o3;
    __half2 h01 = __floats2half2_rn(o0, o1);
    __half2 h23 = __floats2half2_rn(o2, o3);
    uint2 w = make_uint2(*(uint32_t*)&h01, *(uint32_t*)&h23);
    *(uint2*)(O + (size_t)node * HV + t * 4) = w;
}

// ---------------- pooling: column-wise sum and max of h (fp16 in, fp32 accum) ------
__device__ __forceinline__ void atomicMaxF(float* addr, float val) {
    int* ia = (int*)addr;
    int old = *ia;
    while (__int_as_float(old) < val) {
        int assumed = old;
        old = atomicCAS(ia, assumed, __float_as_int(val));
        if (old == assumed) break;
    }
}

__global__ void k_pool(const __half* __restrict__ H) {
    int t = threadIdx.x;  // 256
    float sum = 0.0f;
    float mx  = __int_as_float(0xff800000);
    for (int r = blockIdx.x; r < NV; r += gridDim.x) {
        float v = __half2float(H[(size_t)r * HV + t]);
        sum += v;
        mx = fmaxf(mx, v);
    }
    atomicAdd(&g_pooled[t], sum);
    atomicMaxF(&g_pooled[HV + t], mx);
}

__global__ void k_pick(const __half* __restrict__ H, const int* __restrict__ node_index) {
    int t = threadIdx.x;  // 256
    int ni = node_index[0];
    g_pooled[2 * HV + t] = __half2float(H[(size_t)ni * HV + t]);
}

// ---------------- head GEMV: fd[1024] = pooled[768] @ Wg[768,1024] + bg ----------------
__global__ void k_gemv(const float* __restrict__ Wg, const float* __restrict__ bg) {
    __shared__ float sp[3 * HV];
    int t = threadIdx.x;  // 256, grid 4
    for (int i = t; i < 3 * HV; i += 256) sp[i] = g_pooled[i];
    __syncthreads();
    int j = blockIdx.x * 256 + t;
    float acc = bg[j];
    #pragma unroll 8
    for (int k = 0; k < 3 * HV; k++) acc += sp[k] * Wg[(size_t)k * (2 * FV) + j];
    g_fd[j] = acc;
}

// ---------------- epilogue: reparam + log_prob ----------------
__global__ void k_final(const float* __restrict__ eps, float* __restrict__ out) {
    __shared__ float red[FV];
    int t = threadIdx.x;  // 512
    float mu = g_fd[t];
    float sg = fabsf(g_fd[FV + t]);
    float fn = mu + sg * eps[t];
    out[t]          = fn;
    out[FV + t]     = mu;
    out[2 * FV + t] = sg;
    float z = (fn - mu) / sg;
    const float half_log2pi = 0.9189385332046727f;
    float term = -0.5f * z * z - logf(sg) - half_log2pi;
    red[t] = term;
    __syncthreads();
    #pragma unroll
    for (int o = 256; o > 0; o >>= 1) {
        if (t < o) red[t] += red[t + o];
        __syncthreads();
    }
    if (t == 0) out[3 * FV] = red[0] / (float)FV;
}

// ---------------- launch ----------------
extern "C" void kernel_launch(void* const* d_in, const int* in_sizes, int n_in,
                              void* d_out, int out_size) {
    const float* feat       = (const float*)d_in[0];
    const int*   src        = (const int*)  d_in[1];
    const int*   dst        = (const int*)  d_in[2];
    const int*   node_index = (const int*)  d_in[3];
    const float* W1         = (const float*)d_in[4];
    const float* b1         = (const float*)d_in[5];
    const float* W2         = (const float*)d_in[6];
    const float* b2         = (const float*)d_in[7];
    const float* Wg         = (const float*)d_in[8];
    const float* bg         = (const float*)d_in[9];
    const float* eps        = (const float*)d_in[10];
    float*       out        = (float*)d_out;

    void *yp_v, *hp_v, *w1p_v, *w2p_v;
    cudaGetSymbolAddress(&yp_v, g_yh);
    cudaGetSymbolAddress(&hp_v, g_hh);
    cudaGetSymbolAddress(&w1p_v, g_wt1);
    cudaGetSymbolAddress(&w2p_v, g_wt2);
    __half*   yp  = (__half*)yp_v;
    __half*   hp  = (__half*)hp_v;
    uint32_t* w1p = (uint32_t*)w1p_v;
    uint32_t* w2p = (uint32_t*)w2p_v;

    dim3 gemm_grid(2, (NV + 127) / 128);

    k_init<<<(NV + 255) / 256, 256>>>(W1, W2);
    k_deg<<<(EV + 255) / 256, 256>>>(src, dst);
    k_norm<<<(NV + 255) / 256, 256>>>();
    // GEMM1 at launch slot #4 for the fixed-index ncu capture
    k_gemm<false><<<gemm_grid, 256>>>(feat, nullptr, w1p, yp, NV, FV);
    k_scan1<<<NB_SCAN, 256>>>();
    k_scan2<<<1, 512>>>();
    k_scan3<<<NB_SCAN, 256>>>();
    k_scatter<<<(EV + 255) / 256, 256>>>(src, dst);

    k_agg<<<NV, 64>>>(yp, b1, hp);
    k_gemm<true><<<gemm_grid, 256>>>(nullptr, hp, w2p, yp, NV, HV);
    k_agg<<<NV, 64>>>(yp, b2, hp);

    k_pool<<<256, 256>>>(hp);
    k_pick<<<1, 256>>>(hp, node_index);
    k_gemv<<<4, 256>>>(Wg, bg);
    k_final<<<1, 512>>>(eps, out);
}

// round 11
// speedup vs baseline: 1.4919x; 1.0879x over previous
#include <cuda_runtime.h>
#include <cuda_fp16.h>
#include <cstdint>

// Problem constants (fixed by dataset)
#define NV 100000
#define EV 1600000
#define FV 512
#define HV 256
#define NB_SCAN ((NV + 255) / 256)   // 391

// ---------------- scratch (static device globals; no allocation) ----------------
__device__ int   g_out_deg[NV];
__device__ int   g_in_deg[NV];
__device__ float g_norm_src[NV];
__device__ float g_norm_dst[NV];
__device__ int   g_offsets[NV];
__device__ int   g_cursor[NV];
__device__ int   g_part[NB_SCAN];
__device__ int   g_sorted_src[EV];
__device__ __align__(16) __half g_yh[(size_t)NV * HV];  // pre-aggregation activations (fp16)
__device__ __align__(16) __half g_hh[(size_t)NV * HV];  // post-aggregation activations (fp16)
__device__ __align__(16) uint32_t g_wt1[HV * (FV / 2)]; // W1^T as fp16x2: [n][k/2]
__device__ __align__(16) uint32_t g_wt2[HV * (HV / 2)]; // W2^T as fp16x2
__device__ float g_pooled[3 * HV];
__device__ float g_fd[2 * FV];

// ---------------- init + weight transpose + fd bias seed ----------------
__global__ void k_init(const float* __restrict__ W1, const float* __restrict__ W2,
                       const float* __restrict__ bg) {
    int i = blockIdx.x * blockDim.x + threadIdx.x;
    if (i < NV) { g_out_deg[i] = 0; g_in_deg[i] = 0; g_cursor[i] = 0; }
    if (i < HV) { g_pooled[i] = 0.0f; g_pooled[HV + i] = __int_as_float(0xff800000); } // -inf
    if (i < 2 * FV) g_fd[i] = bg[i];
    if (i < HV * (FV / 2)) {
        int n  = i / (FV / 2);
        int kp = i % (FV / 2);
        __half2 h = __floats2half2_rn(W1[(size_t)(2 * kp) * HV + n],
                                      W1[(size_t)(2 * kp + 1) * HV + n]);
        g_wt1[i] = *(uint32_t*)&h;
    }
    if (i < HV * (HV / 2)) {
        int n  = i / (HV / 2);
        int kp = i % (HV / 2);
        __half2 h = __floats2half2_rn(W2[(size_t)(2 * kp) * HV + n],
                                      W2[(size_t)(2 * kp + 1) * HV + n]);
        g_wt2[i] = *(uint32_t*)&h;
    }
}

__global__ void k_deg(const int* __restrict__ src, const int* __restrict__ dst) {
    int e = blockIdx.x * blockDim.x + threadIdx.x;
    if (e < EV) {
        atomicAdd(&g_out_deg[src[e]], 1);
        atomicAdd(&g_in_deg[dst[e]], 1);
    }
}

__global__ void k_norm() {
    int i = blockIdx.x * blockDim.x + threadIdx.x;
    if (i < NV) {
        g_norm_src[i] = rsqrtf(fmaxf((float)g_out_deg[i], 1.0f));
        g_norm_dst[i] = rsqrtf(fmaxf((float)g_in_deg[i], 1.0f));
    }
}

// ---------------- exclusive scan of in_deg -> offsets ----------------
__global__ void k_scan1() {
    __shared__ int s[256];
    int t = threadIdx.x;
    int i = blockIdx.x * 256 + t;
    int v = (i < NV) ? g_in_deg[i] : 0;
    s[t] = v;
    __syncthreads();
    #pragma unroll
    for (int off = 1; off < 256; off <<= 1) {
        int x = (t >= off) ? s[t - off] : 0;
        __syncthreads();
        s[t] += x;
        __syncthreads();
    }
    if (i < NV) g_offsets[i] = s[t] - v;
    if (t == 255) g_part[blockIdx.x] = s[255];
}

__global__ void k_scan2() {
    __shared__ int s[512];
    int t = threadIdx.x;
    int v = (t < NB_SCAN) ? g_part[t] : 0;
    s[t] = v;
    __syncthreads();
    #pragma unroll
    for (int off = 1; off < 512; off <<= 1) {
        int x = (t >= off) ? s[t - off] : 0;
        __syncthreads();
        s[t] += x;
        __syncthreads();
    }
    if (t < NB_SCAN) g_part[t] = s[t] - v;
}

__global__ void k_scan3() {
    int t = threadIdx.x;
    int i = blockIdx.x * 256 + t;
    if (i < NV) g_offsets[i] += g_part[blockIdx.x];
}

__global__ void k_scatter(const int* __restrict__ src, const int* __restrict__ dst) {
    int e = blockIdx.x * blockDim.x + threadIdx.x;
    if (e < EV) {
        int d = dst[e];
        int p = atomicAdd(&g_cursor[d], 1);
        g_sorted_src[g_offsets[d] + p] = src[e];
    }
}

// ---------------- fp16 mma GEMM: BK=32, single sync/tile, ldmatrix + cp.async ----
#define SRS2 20   // smem row stride in 32-bit words (16 data + 4 pad; ldsm conflict-free)

__device__ __forceinline__ void mma_f16(float* c, const uint32_t* a, const uint32_t* b) {
    asm volatile(
        "mma.sync.aligned.m16n8k16.row.col.f32.f16.f16.f32 "
        "{%0,%1,%2,%3}, {%4,%5,%6,%7}, {%8,%9}, {%0,%1,%2,%3};"
        : "+f"(c[0]), "+f"(c[1]), "+f"(c[2]), "+f"(c[3])
        : "r"(a[0]), "r"(a[1]), "r"(a[2]), "r"(a[3]), "r"(b[0]), "r"(b[1]));
}

__device__ __forceinline__ void ldsm_x4(uint32_t* r, uint32_t saddr) {
    asm volatile("ldmatrix.sync.aligned.m8n8.x4.shared.b16 {%0,%1,%2,%3}, [%4];"
                 : "=r"(r[0]), "=r"(r[1]), "=r"(r[2]), "=r"(r[3]) : "r"(saddr));
}

__device__ __forceinline__ void cp_async16(uint32_t dst, const void* src) {
    asm volatile("cp.async.ca.shared.global [%0], [%1], 16;" :: "r"(dst), "l"(src) : "memory");
}

__device__ __forceinline__ void sts_v4(uint32_t addr, uint4 w) {
    asm volatile("st.shared.v4.b32 [%0], {%1,%2,%3,%4};"
                 :: "r"(addr), "r"(w.x), "r"(w.y), "r"(w.z), "r"(w.w) : "memory");
}

template <bool AHALF>
__global__ __launch_bounds__(256, 2) void k_gemm(const float*  __restrict__ Af,
                                                 const __half* __restrict__ Ah,
                                                 const uint32_t* __restrict__ Wt,
                                                 __half* __restrict__ C,
                                                 int M, int K) {
    __shared__ uint32_t As[2][128 * SRS2];   // [m][kp 0..15] packed fp16x2
    __shared__ uint32_t Bs[2][128 * SRS2];   // [n][kp 0..15]

    int tid  = threadIdx.x;
    int brow = blockIdx.y * 128;
    int bcol = blockIdx.x * 128;
    int Kp   = K >> 1;                       // K in fp16x2 words

    uint32_t as_base = (uint32_t)__cvta_generic_to_shared(&As[0][0]);
    uint32_t bs_base = (uint32_t)__cvta_generic_to_shared(&Bs[0][0]);
    const uint32_t BUFB = 128 * SRS2 * 4;    // bytes per buffer

    // ---- A mapping: row = tid/2, 16 k-halves per thread ----
    int arow  = tid >> 1;
    int ahalf = tid & 1;                     // 0: k 0..15 of tile, 1: k 16..31
    int gr = brow + arow;
    bool v = gr < M;
    const float*    Apf = AHALF ? nullptr : (Af + (size_t)(v ? gr : 0) * K  + ahalf * 16);
    const uint32_t* Aph = AHALF ? ((const uint32_t*)Ah + (size_t)(v ? gr : 0) * Kp + ahalf * 8) : nullptr;
    uint32_t a_st = as_base + (arow * SRS2 + ahalf * 8) * 4;

    // ---- B cp.async mapping: n = tid/2, 32B (16 k-halves) per thread (2x16B) ----
    int bn    = tid >> 1;
    int bhalf = tid & 1;
    const uint32_t* Bp = Wt + (size_t)(bcol + bn) * Kp + bhalf * 8;
    uint32_t b_st = bs_base + (bn * SRS2 + bhalf * 8) * 4;

    // ---- warp tiling: 8 warps (4m x 2n), each 32x64 ----
    int wid  = tid >> 5, lane = tid & 31;
    int wm = (wid & 3) * 32;
    int wn = (wid >> 2) * 64;
    int r  = lane >> 2;
    int cq = lane & 3;

    // ldmatrix byte offsets within a buffer (ks adds 32B = 8 words)
    uint32_t a_ld_off0 = ((wm + (lane & 15)) * SRS2 + (lane >> 4) * 4) * 4;
    uint32_t a_ld_off1 = ((wm + 16 + (lane & 15)) * SRS2 + (lane >> 4) * 4) * 4;
    int bn_in = (lane & 7) + ((lane >> 4) << 3);
    int bk_in = (lane >> 3) & 1;
    uint32_t b_ld_off[4];
    #pragma unroll
    for (int j = 0; j < 4; j++)
        b_ld_off[j] = ((wn + j * 16 + bn_in) * SRS2 + bk_in * 4) * 4;

    float acc[2][8][4];
    #pragma unroll
    for (int i = 0; i < 2; i++)
        #pragma unroll
        for (int j = 0; j < 8; j++)
            #pragma unroll
            for (int q = 0; q < 4; q++) acc[i][j][q] = 0.0f;

    float4 pa[4];   // f32 A prefetch regs (GEMM1 path only)

    // prologue: tile 0 loads
    if (AHALF) {
        // A(0) straight to smem via cp.async (no reg round-trip)
        cp_async16(a_st,      Aph);
        cp_async16(a_st + 16, Aph + 4);
    } else {
        #pragma unroll
        for (int i = 0; i < 4; i++)
            pa[i] = v ? *(const float4*)(Apf + i * 4) : make_float4(0,0,0,0);
    }
    cp_async16(b_st,      Bp);
    cp_async16(b_st + 16, Bp + 4);
    asm volatile("cp.async.commit_group;" ::: "memory");

    int buf = 0;
    for (int k0 = 0; k0 < K; k0 += 32) {
        if (!AHALF) {
            // store A(k0) from regs (cvt to fp16) into As[buf]
            uint32_t ast = a_st + buf * BUFB;
            __half2 h0 = __floats2half2_rn(pa[0].x, pa[0].y);
            __half2 h1 = __floats2half2_rn(pa[0].z, pa[0].w);
            __half2 h2 = __floats2half2_rn(pa[1].x, pa[1].y);
            __half2 h3 = __floats2half2_rn(pa[1].z, pa[1].w);
            __half2 h4 = __floats2half2_rn(pa[2].x, pa[2].y);
            __half2 h5 = __floats2half2_rn(pa[2].z, pa[2].w);
            __half2 h6 = __floats2half2_rn(pa[3].x, pa[3].y);
            __half2 h7 = __floats2half2_rn(pa[3].z, pa[3].w);
            sts_v4(ast,      make_uint4(*(uint32_t*)&h0, *(uint32_t*)&h1, *(uint32_t*)&h2, *(uint32_t*)&h3));
            sts_v4(ast + 16, make_uint4(*(uint32_t*)&h4, *(uint32_t*)&h5, *(uint32_t*)&h6, *(uint32_t*)&h7));
        }

        asm volatile("cp.async.wait_group 0;" ::: "memory");   // tile k0 async loads landed
        __syncthreads();                                       // single barrier per tile

        int kn = k0 + 32;
        if (kn < K) {
            // issue next-tile loads into buf^1 (safe: after the sync)
            if (AHALF) {
                uint32_t adst = a_st + (buf ^ 1) * BUFB;
                cp_async16(adst,      Aph + (kn >> 1));
                cp_async16(adst + 16, Aph + (kn >> 1) + 4);
            } else {
                #pragma unroll
                for (int i = 0; i < 4; i++)
                    pa[i] = v ? *(const float4*)(Apf + kn + i * 4) : make_float4(0,0,0,0);
            }
            uint32_t bdst = b_st + (buf ^ 1) * BUFB;
            cp_async16(bdst,      Bp + (kn >> 1));
            cp_async16(bdst + 16, Bp + (kn >> 1) + 4);
            asm volatile("cp.async.commit_group;" ::: "memory");
        }

        // compute: 2 k-steps of m16n8k16
        uint32_t abase = as_base + buf * BUFB;
        uint32_t bbase = bs_base + buf * BUFB;
        #pragma unroll
        for (int ks = 0; ks < 2; ks++) {
            uint32_t koff = ks * 32;   // 8 words
            uint32_t a[2][4], b[8][2];
            ldsm_x4(a[0], abase + a_ld_off0 + koff);
            ldsm_x4(a[1], abase + a_ld_off1 + koff);
            #pragma unroll
            for (int j = 0; j < 4; j++) {
                uint32_t rr[4];
                ldsm_x4(rr, bbase + b_ld_off[j] + koff);
                b[2*j][0]   = rr[0];
                b[2*j][1]   = rr[1];
                b[2*j+1][0] = rr[2];
                b[2*j+1][1] = rr[3];
            }
            #pragma unroll
            for (int mt = 0; mt < 2; mt++)
                #pragma unroll
                for (int nt = 0; nt < 8; nt++)
                    mma_f16(acc[mt][nt], a[mt], b[nt]);
        }
        buf ^= 1;
        // no second __syncthreads(): next store targets buf^1, last read 2 iters ago
    }

    // ---- epilogue: scale by norm_src[row], convert fp16 RN, store ----
    #pragma unroll
    for (int mt = 0; mt < 2; mt++) {
        int row0 = brow + wm + mt * 16 + r;
        int row1 = row0 + 8;
        float s0 = (row0 < M) ? g_norm_src[row0] : 0.0f;
        float s1 = (row1 < M) ? g_norm_src[row1] : 0.0f;
        #pragma unroll
        for (int nt = 0; nt < 8; nt++) {
            int col = bcol + wn + nt * 8 + cq * 2;
            if (row0 < M)
                *(__half2*)(C + (size_t)row0 * HV + col) =
                    __floats2half2_rn(acc[mt][nt][0] * s0, acc[mt][nt][1] * s0);
            if (row1 < M)
                *(__half2*)(C + (size_t)row1 * HV + col) =
                    __floats2half2_rn(acc[mt][nt][2] * s1, acc[mt][nt][3] * s1);
        }
    }
}

// ---------------- aggregation: warp-per-node, uint4 (16B) lane loads ----------------
// h[n] = leaky( norm_dst[n] * sum_{e in CSR(n)} Y[src_e] + bias ), fp16 out.
__global__ void k_agg(const __half* __restrict__ Y, const float* __restrict__ bias,
                      __half* __restrict__ O) {
    int node = blockIdx.x * 4 + (threadIdx.x >> 5);
    if (node >= NV) return;
    int lane = threadIdx.x & 31;            // 8 cols per lane via uint4
    int start = g_offsets[node];
    int cnt   = g_in_deg[node];
    const uint4* Yv = (const uint4*)Y;      // row stride = 32 uint4

    float acc[4][8];
    #pragma unroll
    for (int i = 0; i < 4; i++)
        #pragma unroll
        for (int j = 0; j < 8; j++) acc[i][j] = 0.0f;

    int e = 0;
    for (; e + 4 <= cnt; e += 4) {
        int s0 = g_sorted_src[start + e];
        int s1 = g_sorted_src[start + e + 1];
        int s2 = g_sorted_src[start + e + 2];
        int s3 = g_sorted_src[start + e + 3];
        uint4 u0 = Yv[(size_t)s0 * 32 + lane];
        uint4 u1 = Yv[(size_t)s1 * 32 + lane];
        uint4 u2 = Yv[(size_t)s2 * 32 + lane];
        uint4 u3 = Yv[(size_t)s3 * 32 + lane];
        #pragma unroll
        for (int w = 0; w < 4; w++) {
            float2 f0 = __half22float2(*((__half2*)&u0 + w));
            float2 f1 = __half22float2(*((__half2*)&u1 + w));
            float2 f2 = __half22float2(*((__half2*)&u2 + w));
            float2 f3 = __half22float2(*((__half2*)&u3 + w));
            acc[0][2*w]   += f0.x; acc[0][2*w+1] += f0.y;
            acc[1][2*w]   += f1.x; acc[1][2*w+1] += f1.y;
            acc[2][2*w]   += f2.x; acc[2][2*w+1] += f2.y;
            acc[3][2*w]   += f3.x; acc[3][2*w+1] += f3.y;
        }
    }
    for (; e < cnt; e++) {
        int s0 = g_sorted_src[start + e];
        uint4 u0 = Yv[(size_t)s0 * 32 + lane];
        #pragma unroll
        for (int w = 0; w < 4; w++) {
            float2 f0 = __half22float2(*((__half2*)&u0 + w));
            acc[0][2*w]   += f0.x; acc[0][2*w+1] += f0.y;
        }
    }
    #pragma unroll
    for (int j = 0; j < 8; j++) acc[0][j] += acc[1][j] + acc[2][j] + acc[3][j];

    float nd = g_norm_dst[node];
    float4 bb0 = *(const float4*)(bias + lane * 8);
    float4 bb1 = *(const float4*)(bias + lane * 8 + 4);
    float o[8];
    o[0] = acc[0][0] * nd + bb0.x;
    o[1] = acc[0][1] * nd + bb0.y;
    o[2] = acc[0][2] * nd + bb0.z;
    o[3] = acc[0][3] * nd + bb0.w;
    o[4] = acc[0][4] * nd + bb1.x;
    o[5] = acc[0][5] * nd + bb1.y;
    o[6] = acc[0][6] * nd + bb1.z;
    o[7] = acc[0][7] * nd + bb1.w;
    #pragma unroll
    for (int j = 0; j < 8; j++) o[j] = (o[j] >= 0.0f) ? o[j] : 0.01f * o[j];

    __half2 h0 = __floats2half2_rn(o[0], o[1]);
    __half2 h1 = __floats2half2_rn(o[2], o[3]);
    __half2 h2 = __floats2half2_rn(o[4], o[5]);
    __half2 h3 = __floats2half2_rn(o[6], o[7]);
    *(uint4*)(O + (size_t)node * HV + lane * 8) =
        make_uint4(*(uint32_t*)&h0, *(uint32_t*)&h1, *(uint32_t*)&h2, *(uint32_t*)&h3);
}

// ---------------- pooling ----------------
__device__ __forceinline__ void atomicMaxF(float* addr, float val) {
    int* ia = (int*)addr;
    int old = *ia;
    while (__int_as_float(old) < val) {
        int assumed = old;
        old = atomicCAS(ia, assumed, __float_as_int(val));
        if (old == assumed) break;
    }
}

__global__ void k_pool(const __half* __restrict__ H) {
    int t = threadIdx.x;  // 256
    float sum = 0.0f;
    float mx  = __int_as_float(0xff800000);
    for (int r = blockIdx.x; r < NV; r += gridDim.x) {
        float v = __half2float(H[(size_t)r * HV + t]);
        sum += v;
        mx = fmaxf(mx, v);
    }
    atomicAdd(&g_pooled[t], sum);
    atomicMaxF(&g_pooled[HV + t], mx);
}

__global__ void k_pick(const __half* __restrict__ H, const int* __restrict__ node_index) {
    int t = threadIdx.x;  // 256
    int ni = node_index[0];
    g_pooled[2 * HV + t] = __half2float(H[(size_t)ni * HV + t]);
}

// ---------------- head GEMV (split-k, 32 blocks, atomic partials; bias pre-seeded) ----
__global__ void k_gemv(const float* __restrict__ Wg) {
    __shared__ float sp[96];
    int t = threadIdx.x;              // 256
    int jb = blockIdx.x & 3;          // output block
    int kb = blockIdx.x >> 2;         // k chunk (8 x 96)
    for (int i = t; i < 96; i += 256) sp[i] = g_pooled[kb * 96 + i];
    __syncthreads();
    int j = jb * 256 + t;
    float acc = 0.0f;
    #pragma unroll 8
    for (int k = 0; k < 96; k++)
        acc += sp[k] * Wg[(size_t)(kb * 96 + k) * (2 * FV) + j];
    atomicAdd(&g_fd[j], acc);
}

// ---------------- epilogue: reparam + log_prob ----------------
__global__ void k_final(const float* __restrict__ eps, float* __restrict__ out) {
    __shared__ float red[FV];
    int t = threadIdx.x;  // 512
    float mu = g_fd[t];
    float sg = fabsf(g_fd[FV + t]);
    float fn = mu + sg * eps[t];
    out[t]          = fn;
    out[FV + t]     = mu;
    out[2 * FV + t] = sg;
    float z = (fn - mu) / sg;
    const float half_log2pi = 0.9189385332046727f;
    float term = -0.5f * z * z - logf(sg) - half_log2pi;
    red[t] = term;
    __syncthreads();
    #pragma unroll
    for (int o = 256; o > 0; o >>= 1) {
        if (t < o) red[t] += red[t + o];
        __syncthreads();
    }
    if (t == 0) out[3 * FV] = red[0] / (float)FV;
}

// ---------------- launch ----------------
extern "C" void kernel_launch(void* const* d_in, const int* in_sizes, int n_in,
                              void* d_out, int out_size) {
    const float* feat       = (const float*)d_in[0];
    const int*   src        = (const int*)  d_in[1];
    const int*   dst        = (const int*)  d_in[2];
    const int*   node_index = (const int*)  d_in[3];
    const float* W1         = (const float*)d_in[4];
    const float* b1         = (const float*)d_in[5];
    const float* W2         = (const float*)d_in[6];
    const float* b2         = (const float*)d_in[7];
    const float* Wg         = (const float*)d_in[8];
    const float* bg         = (const float*)d_in[9];
    const float* eps        = (const float*)d_in[10];
    float*       out        = (float*)d_out;

    void *yp_v, *hp_v, *w1p_v, *w2p_v;
    cudaGetSymbolAddress(&yp_v, g_yh);
    cudaGetSymbolAddress(&hp_v, g_hh);
    cudaGetSymbolAddress(&w1p_v, g_wt1);
    cudaGetSymbolAddress(&w2p_v, g_wt2);
    __half*   yp  = (__half*)yp_v;
    __half*   hp  = (__half*)hp_v;
    uint32_t* w1p = (uint32_t*)w1p_v;
    uint32_t* w2p = (uint32_t*)w2p_v;

    dim3 gemm_grid(2, (NV + 127) / 128);
    int agg_grid = (NV + 3) / 4;

    k_init<<<(NV + 255) / 256, 256>>>(W1, W2, bg);
    k_deg<<<(EV + 255) / 256, 256>>>(src, dst);
    k_norm<<<(NV + 255) / 256, 256>>>();
    // GEMM1 at launch slot #4 for the fixed-index ncu capture
    k_gemm<false><<<gemm_grid, 256>>>(feat, nullptr, w1p, yp, NV, FV);
    k_scan1<<<NB_SCAN, 256>>>();
    k_scan2<<<1, 512>>>();
    k_scan3<<<NB_SCAN, 256>>>();
    k_scatter<<<(EV + 255) / 256, 256>>>(src, dst);

    k_agg<<<agg_grid, 128>>>(yp, b1, hp);
    k_gemm<true><<<gemm_grid, 256>>>(nullptr, hp, w2p, yp, NV, HV);
    k_agg<<<agg_grid, 128>>>(yp, b2, hp);

    k_pool<<<256, 256>>>(hp);
    k_pick<<<1, 256>>>(hp, node_index);
    k_gemv<<<32, 256>>>(Wg);
    k_final<<<1, 512>>>(eps, out);
}